// round 1
// baseline (speedup 1.0000x reference)
#include <cuda_runtime.h>
#include <math.h>

// ---------------- problem constants (fixed by reference) ----------------
#define VOCAB   50000
#define B_DOCS  128
#define LSEQ    350
#define NGW     3
#define DIM     768
#define HID     256
#define CLS     20
#define HEADS   8
#define LAYERS  2
#define KHOPS   3
#define ALPHA   0.15f
#define NNODES  (B_DOCS*LSEQ)      // 44800
#define WIN     7                  // 2*NGW+1

// ---------------- scratch (device globals; no allocation allowed) -------
__device__ float g_x  [NNODES*HID];          // 45.9 MB  post-ReLU hidden
__device__ float g_h  [NNODES*CLS];          // node features between layers
__device__ float g_z  [NNODES*HEADS*CLS];    // per-head projected features (z0)
__device__ float g_zt0[NNODES*HEADS*CLS];    // diffusion ping
__device__ float g_zt1[NNODES*HEADS*CLS];    // diffusion pong
__device__ float g_es [NNODES*HEADS];        // src attention logits
__device__ float g_ed [NNODES*HEADS];        // dst attention logits
__device__ float g_att[NNODES*HEADS*WIN];    // normalized edge attention (banded)

// ---------------- K1: fused gather + GEMM1 + bias + ReLU -----------------
// x[n, :] = relu(emb[node_ids[n], :] @ W1 + b1)   [44800,768]x[768,256]
#define BM 128
#define BN 64
#define BK 16
#define BMP (BM+4)   // pad for bank conflicts, keeps 16B alignment

__global__ __launch_bounds__(256) void k_gemm1(
    const int* __restrict__ node_ids, const float* __restrict__ emb,
    const float* __restrict__ W1, const float* __restrict__ b1)
{
    __shared__ float As[BK][BMP];
    __shared__ float Bs[BK][BN];
    __shared__ int   rows[BM];

    const int t  = threadIdx.x;
    const int m0 = blockIdx.y * BM;
    const int n0 = blockIdx.x * BN;
    if (t < BM) rows[t] = node_ids[m0 + t];

    const int tx = t & 15;        // 0..15 -> n group (4 cols each)
    const int ty = t >> 4;        // 0..15 -> m group (8 rows each)

    float acc[8][4];
    #pragma unroll
    for (int i = 0; i < 8; i++)
        #pragma unroll
        for (int j = 0; j < 4; j++) acc[i][j] = 0.f;

    for (int k0 = 0; k0 < DIM; k0 += BK) {
        __syncthreads();   // protect smem from previous compute / rows load
        // load A tile: 128 rows x 16 k (512 float4, 2 per thread), transposed
        #pragma unroll
        for (int s = t; s < 512; s += 256) {
            int row = s >> 2, c4 = s & 3;
            float4 v = *reinterpret_cast<const float4*>(
                &emb[rows[row]*DIM + k0 + c4*4]);
            As[c4*4+0][row] = v.x;
            As[c4*4+1][row] = v.y;
            As[c4*4+2][row] = v.z;
            As[c4*4+3][row] = v.w;
        }
        // load B tile: 16 k x 64 n (256 float4, 1 per thread)
        {
            int row = t >> 4, c4 = t & 15;
            float4 v = *reinterpret_cast<const float4*>(
                &W1[(k0+row)*HID + n0 + c4*4]);
            *reinterpret_cast<float4*>(&Bs[row][c4*4]) = v;
        }
        __syncthreads();
        #pragma unroll
        for (int kk = 0; kk < BK; kk++) {
            float4 a0 = *reinterpret_cast<const float4*>(&As[kk][ty*8]);
            float4 a1 = *reinterpret_cast<const float4*>(&As[kk][ty*8+4]);
            float4 b0 = *reinterpret_cast<const float4*>(&Bs[kk][tx*4]);
            float a[8] = {a0.x,a0.y,a0.z,a0.w,a1.x,a1.y,a1.z,a1.w};
            float b[4] = {b0.x,b0.y,b0.z,b0.w};
            #pragma unroll
            for (int i = 0; i < 8; i++)
                #pragma unroll
                for (int j = 0; j < 4; j++)
                    acc[i][j] = fmaf(a[i], b[j], acc[i][j]);
        }
    }
    // epilogue: bias + relu
    float bias[4];
    #pragma unroll
    for (int j = 0; j < 4; j++) bias[j] = b1[n0 + tx*4 + j];
    #pragma unroll
    for (int i = 0; i < 8; i++) {
        int m = m0 + ty*8 + i;
        float* o = &g_x[m*HID + n0 + tx*4];
        #pragma unroll
        for (int j = 0; j < 4; j++) {
            float v = acc[i][j] + bias[j];
            o[j] = v > 0.f ? v : 0.f;
        }
    }
}

// ---------------- K2: GEMM2  h = x @ W2 + b2  [N,256]x[256,20] -----------
__global__ __launch_bounds__(256) void k_gemm2(
    const float* __restrict__ W2, const float* __restrict__ b2)
{
    __shared__ float Ws[HID*CLS];   // 20 KB
    for (int i = threadIdx.x; i < HID*CLS; i += 256) Ws[i] = W2[i];
    __syncthreads();
    int idx = blockIdx.x*256 + threadIdx.x;       // N*CLS = 896000 exact
    int n = idx / CLS, c = idx % CLS;
    const float* xr = g_x + n*HID;
    float acc = b2[c];
    #pragma unroll 8
    for (int k = 0; k < HID; k++) acc = fmaf(xr[k], Ws[k*CLS + c], acc);
    g_h[idx] = acc;
}

// ---------------- K3: per-head projection + attention logits -------------
// z[h,n,:] = h[n,:] @ W[l,h];  es = z.a_src, ed = z.a_dst
#define WPAD 404   // per-head padded stride to dodge bank conflicts
__global__ __launch_bounds__(256) void k_zscore(
    const float* __restrict__ gat_W, const float* __restrict__ a_src,
    const float* __restrict__ a_dst, int layer)
{
    __shared__ float Ws[HEADS*WPAD];
    __shared__ float as_s[HEADS*CLS], ad_s[HEADS*CLS];
    __shared__ float hs[32*CLS];
    const int t = threadIdx.x;
    const float* Wl = gat_W + layer*HEADS*CLS*CLS;
    for (int i = t; i < HEADS*CLS*CLS; i += 256) {
        int hd = i / (CLS*CLS), r = i % (CLS*CLS);
        Ws[hd*WPAD + r] = Wl[i];
    }
    for (int i = t; i < HEADS*CLS; i += 256) {
        as_s[i] = a_src[layer*HEADS*CLS + i];
        ad_s[i] = a_dst[layer*HEADS*CLS + i];
    }
    const int n0 = blockIdx.x * 32;
    for (int i = t; i < 32*CLS; i += 256) hs[i] = g_h[n0*CLS + i];
    __syncthreads();

    const int hd = t & 7, ni = t >> 3;
    const int n = n0 + ni;
    const float* hrow = hs + ni*CLS;
    const float* W = Ws + hd*WPAD;
    float zrow[CLS];
    #pragma unroll
    for (int c = 0; c < CLS; c++) zrow[c] = 0.f;
    #pragma unroll
    for (int c2 = 0; c2 < CLS; c2++) {
        float hv = hrow[c2];
        #pragma unroll
        for (int c = 0; c < CLS; c++)
            zrow[c] = fmaf(hv, W[c2*CLS + c], zrow[c]);
    }
    float es = 0.f, ed = 0.f;
    #pragma unroll
    for (int c = 0; c < CLS; c++) {
        es = fmaf(zrow[c], as_s[hd*CLS + c], es);
        ed = fmaf(zrow[c], ad_s[hd*CLS + c], ed);
    }
    float* zo = g_z   + (n*HEADS + hd)*CLS;
    float* zt = g_zt0 + (n*HEADS + hd)*CLS;
    #pragma unroll
    for (int c = 0; c < CLS; c++) { zo[c] = zrow[c]; zt[c] = zrow[c]; }
    g_es[n*HEADS + hd] = es;
    g_ed[n*HEADS + hd] = ed;
}

// ---------------- K4: banded edge softmax (per dst node, 7-slot window) --
__global__ __launch_bounds__(256) void k_att()
{
    int idx = blockIdx.x*256 + threadIdx.x;   // N*HEADS = 358400 exact
    int n = idx / HEADS, hd = idx % HEADS;
    int pos = n % LSEQ;
    int base = n - pos;
    float ed = g_ed[idx];
    float e[WIN];
    float m = -1e30f;
    #pragma unroll
    for (int w = 0; w < WIN; w++) {
        int j = pos - NGW + w;
        bool valid = (j >= 0) & (j < LSEQ);
        int jj = valid ? j : pos;
        float ev = g_es[(base + jj)*HEADS + hd] + ed;
        ev = ev > 0.f ? ev : 0.2f*ev;          // leaky_relu(0.2)
        e[w] = valid ? ev : -1e30f;
        m = fmaxf(m, e[w]);
    }
    float ex[WIN], s = 0.f;
    #pragma unroll
    for (int w = 0; w < WIN; w++) {
        ex[w] = (e[w] > -1e29f) ? expf(e[w] - m) : 0.f;
        s += ex[w];
    }
    float inv = 1.f / (s + 1e-9f);
    #pragma unroll
    for (int w = 0; w < WIN; w++) g_att[idx*WIN + w] = ex[w]*inv;
}

// ---------------- K5: one attention-diffusion hop (banded SpMV) ----------
// zt_out[n,h,c] = 0.85 * sum_j att[n,h,j] * zt_in[j,h,c] + 0.15 * z0[n,h,c]
__global__ __launch_bounds__(256) void k_diffuse(int hop)
{
    const float* zin  = (hop & 1) ? g_zt1 : g_zt0;
    float*       zout = (hop & 1) ? g_zt0 : g_zt1;
    int idx = blockIdx.x*256 + threadIdx.x;   // N*HEADS*CLS = 7168000 exact
    int n  = idx / (HEADS*CLS);
    int hc = idx % (HEADS*CLS);
    int hd = hc / CLS;
    int pos = n % LSEQ;
    int base = n - pos;
    const float* att = g_att + (n*HEADS + hd)*WIN;
    float acc = 0.f;
    #pragma unroll
    for (int w = 0; w < WIN; w++) {
        int j = pos - NGW + w;
        int jj = j < 0 ? 0 : (j >= LSEQ ? LSEQ-1 : j);  // att[w]==0 if invalid
        acc = fmaf(att[w], zin[(base + jj)*HEADS*CLS + hc], acc);
    }
    zout[idx] = (1.f - ALPHA)*acc + ALPHA*g_z[idx];
}

// ---------------- K6: ELU + mean over heads -> new h ---------------------
__global__ __launch_bounds__(256) void k_merge()
{
    int idx = blockIdx.x*256 + threadIdx.x;   // N*CLS = 896000 exact
    int n = idx / CLS, c = idx % CLS;
    float acc = 0.f;
    #pragma unroll
    for (int hd = 0; hd < HEADS; hd++) {
        float v = g_zt1[(n*HEADS + hd)*CLS + c];   // KHOPS=3 -> result in zt1
        acc += (v > 0.f) ? v : expm1f(v);
    }
    g_h[idx] = acc * (1.f / HEADS);
}

// ---------------- K7: gated weight-and-sum readout per doc ---------------
__global__ __launch_bounds__(256) void k_readout(
    const float* __restrict__ w_gate, const float* __restrict__ b_gate,
    float* __restrict__ out)
{
    __shared__ float wg[CLS];
    __shared__ float sred[240];
    const int t = threadIdx.x;
    if (t < CLS) wg[t] = w_gate[t];
    __syncthreads();
    const int doc = blockIdx.x;
    const float bg = b_gate[0];
    float acc = 0.f;
    if (t < 240) {
        int c = t % CLS, r = t / CLS;   // 12 row-groups x 20 channels
        for (int p = r; p < LSEQ; p += 12) {
            const float* hr = g_h + (doc*LSEQ + p)*CLS;
            float dot = bg;
            #pragma unroll
            for (int k = 0; k < CLS; k++) dot = fmaf(hr[k], wg[k], dot);
            float gate = 1.f / (1.f + expf(-dot));
            acc = fmaf(gate, hr[c], acc);
        }
        sred[t] = acc;
    }
    __syncthreads();
    if (t < CLS) {
        float s = 0.f;
        #pragma unroll
        for (int r = 0; r < 12; r++) s += sred[r*CLS + t];
        out[doc*CLS + t] = s;
    }
}

// ---------------- launch ----------------
extern "C" void kernel_launch(void* const* d_in, const int* in_sizes, int n_in,
                              void* d_out, int out_size)
{
    const int*   node_ids = (const int*)  d_in[0];
    // d_in[1..3]: edge_src / edge_dst / graph_id — structure is implicit (banded), unused
    const float* emb    = (const float*) d_in[4];
    const float* W1     = (const float*) d_in[5];
    const float* b1     = (const float*) d_in[6];
    const float* W2     = (const float*) d_in[7];
    const float* b2     = (const float*) d_in[8];
    const float* gat_W  = (const float*) d_in[9];
    const float* a_src  = (const float*) d_in[10];
    const float* a_dst  = (const float*) d_in[11];
    const float* w_gate = (const float*) d_in[12];
    const float* b_gate = (const float*) d_in[13];
    float* out = (float*)d_out;

    dim3 g1(HID/BN, NNODES/BM);                      // (4, 350)
    k_gemm1<<<g1, 256>>>(node_ids, emb, W1, b1);
    k_gemm2<<<NNODES*CLS/256, 256>>>(W2, b2);        // 3500 blocks
    for (int l = 0; l < LAYERS; l++) {
        k_zscore<<<NNODES/32, 256>>>(gat_W, a_src, a_dst, l);   // 1400
        k_att<<<NNODES*HEADS/256, 256>>>();                     // 1400
        for (int hop = 0; hop < KHOPS; hop++)
            k_diffuse<<<NNODES*HEADS*CLS/256, 256>>>(hop);      // 28000
        k_merge<<<NNODES*CLS/256, 256>>>();                     // 3500
    }
    k_readout<<<B_DOCS, 256>>>(w_gate, b_gate, out);
}

// round 3
// speedup vs baseline: 1.8174x; 1.8174x over previous
#include <cuda_runtime.h>
#include <cuda_bf16.h>
#include <math.h>
#include <stdint.h>

// ---------------- problem constants ----------------
#define VOCAB   50000
#define B_DOCS  128
#define LSEQ    350
#define NGW     3
#define DIM     768
#define HID     256
#define CLS     20
#define HEADS   8
#define LAYERS  2
#define KHOPS   3
#define ALPHA   0.15f
#define NNODES  (B_DOCS*LSEQ)      // 44800
#define WIN     7

// ---------------- scratch ----------------
__device__ float g_h  [NNODES*CLS];                    // node features
__device__ float g_z  [(size_t)HEADS*NNODES*CLS];      // z0 [head][node][cls]
__device__ float g_zt [(size_t)HEADS*NNODES*CLS];      // diffusion result
__device__ float g_es [NNODES*HEADS];
__device__ float g_ed [NNODES*HEADS];
__device__ float g_att[(size_t)HEADS*NNODES*WIN];      // [head][node][win]
__device__ __nv_bfloat16 g_Wth[HID*DIM];               // W1^T hi  [256,768]
__device__ __nv_bfloat16 g_Wtl[HID*DIM];               // W1^T lo

// ---------------- helpers ----------------
__device__ __forceinline__ uint32_t smem_u32(const void* p) {
    uint32_t a;
    asm("{ .reg .u64 t; cvta.to.shared.u64 t, %1; cvt.u32.u64 %0, t; }"
        : "=r"(a) : "l"(p));
    return a;
}
#define SWZ(o) ((o) ^ (((o) >> 3) & 0x70))

__device__ __forceinline__ void ldsm4(uint32_t* r, uint32_t addr) {
    asm volatile("ldmatrix.sync.aligned.m8n8.x4.shared.b16 {%0,%1,%2,%3}, [%4];"
        : "=r"(r[0]), "=r"(r[1]), "=r"(r[2]), "=r"(r[3]) : "r"(addr));
}
__device__ __forceinline__ void mma16816(float* c, const uint32_t* a, const uint32_t* b) {
    asm volatile("mma.sync.aligned.m16n8k16.row.col.f32.bf16.bf16.f32 "
        "{%0,%1,%2,%3}, {%4,%5,%6,%7}, {%8,%9}, {%0,%1,%2,%3};"
        : "+f"(c[0]), "+f"(c[1]), "+f"(c[2]), "+f"(c[3])
        : "r"(a[0]), "r"(a[1]), "r"(a[2]), "r"(a[3]), "r"(b[0]), "r"(b[1]));
}
__device__ __forceinline__ void cpasync16(uint32_t dst, const void* src) {
    size_t gs = __cvta_generic_to_global(src);
    asm volatile("cp.async.cg.shared.global [%0], [%1], 16;"
                 :: "r"(dst), "l"(gs) : "memory");
}
#define CP_COMMIT() asm volatile("cp.async.commit_group;" ::: "memory")
#define CP_WAIT0()  asm volatile("cp.async.wait_group 0;" ::: "memory")

// ---------------- K0: split+transpose W1 -> bf16 hi/lo ----------------
__global__ __launch_bounds__(256) void k_prepw(const float* __restrict__ W1)
{
    int idx = blockIdx.x*256 + threadIdx.x;      // HID*DIM = 196608 exact
    int n = idx / DIM, k = idx % DIM;
    float v = W1[k*HID + n];
    __nv_bfloat16 h = __float2bfloat16_rn(v);
    g_Wth[idx] = h;
    g_Wtl[idx] = __float2bfloat16_rn(v - __bfloat162float(h));
}

// ---------------- K1: gather + GEMM1(mma.sync bf16 3-pass) + GEMM2 ------
#define KB      64
#define NCH     (DIM/KB)            // 12
#define OFF_ROWS 0
#define OFF_B1   512
#define OFF_B2   1536
#define OFF_STG  2048
#define STG_SZ   98304              // AH16K AL16K BH32K BL32K
#define OFF_AH   0
#define OFF_AL   16384
#define OFF_BH   32768
#define OFF_BL   65536
#define GEMM_SMEM (OFF_STG + 2*STG_SZ)   // 198656
#define XS_STRIDE 258
#define OFF_XS   OFF_STG
#define OFF_W2S  (OFF_XS + 128*XS_STRIDE*4)       // +132096 -> 134144
#define OFF_HRED (OFF_W2S + HID*CLS*4)            // +20480  -> 154624

__device__ __forceinline__ uint32_t a_addr(uint32_t base, int row0, int kb, int lane) {
    int q = lane >> 3, lr = lane & 7;
    int row = row0 + ((q & 1) << 3) + lr;
    int k   = kb + ((q >> 1) << 3);
    return base + SWZ((uint32_t)(row*128 + k*2));
}
__device__ __forceinline__ uint32_t b_addr(uint32_t base, int n0, int kb, int lane) {
    int q = lane >> 3, lr = lane & 7;
    int n = n0 + ((q >> 1) << 3) + lr;
    int k = kb + ((q & 1) << 3);
    return base + SWZ((uint32_t)(n*128 + k*2));
}

__device__ __forceinline__ void issue_B(uint32_t stg_u32, int k0, int t) {
    #pragma unroll
    for (int i = 0; i < 8; i++) {
        int idx = t + i*256;             // 0..2047
        int n = idx >> 3, c = idx & 7;
        uint32_t so = SWZ((uint32_t)(n*128 + c*16));
        cpasync16(stg_u32 + OFF_BH + so, g_Wth + (size_t)n*DIM + k0 + c*8);
        cpasync16(stg_u32 + OFF_BL + so, g_Wtl + (size_t)n*DIM + k0 + c*8);
    }
}

__device__ __forceinline__ void load_convert_A(
    char* smc, uint32_t stg_off, const float* __restrict__ emb,
    const int* rows_s, int k0, int t)
{
    int r  = t >> 1;
    int kh = (t & 1) * 32;
    const float4* src = reinterpret_cast<const float4*>(
        emb + (size_t)rows_s[r]*DIM + k0 + kh);
    #pragma unroll
    for (int j = 0; j < 8; j++) {
        float4 v = src[j];
        __nv_bfloat162 h0 = __float22bfloat162_rn(make_float2(v.x, v.y));
        __nv_bfloat162 h1 = __float22bfloat162_rn(make_float2(v.z, v.w));
        float2 f0 = __bfloat1622float2(h0);
        float2 f1 = __bfloat1622float2(h1);
        __nv_bfloat162 l0 = __float22bfloat162_rn(make_float2(v.x-f0.x, v.y-f0.y));
        __nv_bfloat162 l1 = __float22bfloat162_rn(make_float2(v.z-f1.x, v.w-f1.y));
        uint32_t off = SWZ((uint32_t)(r*128 + kh*2 + j*8));
        uint2 hv, lv;
        hv.x = *reinterpret_cast<uint32_t*>(&h0);
        hv.y = *reinterpret_cast<uint32_t*>(&h1);
        lv.x = *reinterpret_cast<uint32_t*>(&l0);
        lv.y = *reinterpret_cast<uint32_t*>(&l1);
        *reinterpret_cast<uint2*>(smc + stg_off + OFF_AH + off) = hv;
        *reinterpret_cast<uint2*>(smc + stg_off + OFF_AL + off) = lv;
    }
}

__global__ __launch_bounds__(256, 1) void k_gemm1tc(
    const int* __restrict__ node_ids, const float* __restrict__ emb,
    const float* __restrict__ b1, const float* __restrict__ W2,
    const float* __restrict__ b2)
{
    extern __shared__ char smc[];
    const uint32_t sb = smem_u32(smc);
    const int t = threadIdx.x, lane = t & 31, wid = t >> 5;
    const int wm = wid >> 2, wn = wid & 3;
    const int m0 = blockIdx.x * 128;
    int*   rows_s = (int*)(smc + OFF_ROWS);
    float* b1s    = (float*)(smc + OFF_B1);
    float* b2s    = (float*)(smc + OFF_B2);

    if (t < 128) rows_s[t] = node_ids[m0 + t];
    b1s[t] = b1[t];
    if (t < CLS) b2s[t] = b2[t];
    __syncthreads();

    float acc[4][8][4];
    #pragma unroll
    for (int mt = 0; mt < 4; mt++)
        #pragma unroll
        for (int nt = 0; nt < 8; nt++)
            #pragma unroll
            for (int q = 0; q < 4; q++) acc[mt][nt][q] = 0.f;

    // prologue: stage 0
    issue_B(sb + OFF_STG, 0, t);
    CP_COMMIT();
    load_convert_A(smc, OFF_STG, emb, rows_s, 0, t);

    for (int ch = 0; ch < NCH; ch++) {
        const uint32_t stg_off = OFF_STG + (ch & 1)*STG_SZ;
        const uint32_t nxt_off = OFF_STG + ((ch + 1) & 1)*STG_SZ;
        CP_WAIT0();
        __syncthreads();
        if (ch < NCH-1) {
            issue_B(sb + nxt_off, (ch + 1)*KB, t);
            CP_COMMIT();
        }
        // ---- compute on current stage ----
        {
            const uint32_t aH = sb + stg_off + OFF_AH;
            const uint32_t aL = sb + stg_off + OFF_AL;
            const uint32_t bH = sb + stg_off + OFF_BH;
            const uint32_t bL = sb + stg_off + OFF_BL;
            #pragma unroll
            for (int ks = 0; ks < 4; ks++) {
                const int kb = ks*16;
                uint32_t af[4][4], bf[8][2], cf[8][2];
                #pragma unroll
                for (int mt = 0; mt < 4; mt++)
                    ldsm4(af[mt], a_addr(aH, wm*64 + mt*16, kb, lane));
                #pragma unroll
                for (int p = 0; p < 4; p++) {
                    uint32_t r[4];
                    ldsm4(r, b_addr(bH, wn*64 + p*16, kb, lane));
                    bf[p*2][0]=r[0]; bf[p*2][1]=r[1];
                    bf[p*2+1][0]=r[2]; bf[p*2+1][1]=r[3];
                }
                #pragma unroll
                for (int mt = 0; mt < 4; mt++)
                    #pragma unroll
                    for (int nt = 0; nt < 8; nt++)
                        mma16816(acc[mt][nt], af[mt], bf[nt]);
                #pragma unroll
                for (int p = 0; p < 4; p++) {
                    uint32_t r[4];
                    ldsm4(r, b_addr(bL, wn*64 + p*16, kb, lane));
                    cf[p*2][0]=r[0]; cf[p*2][1]=r[1];
                    cf[p*2+1][0]=r[2]; cf[p*2+1][1]=r[3];
                }
                #pragma unroll
                for (int mt = 0; mt < 4; mt++)
                    #pragma unroll
                    for (int nt = 0; nt < 8; nt++)
                        mma16816(acc[mt][nt], af[mt], cf[nt]);
                #pragma unroll
                for (int mt = 0; mt < 4; mt++)
                    ldsm4(af[mt], a_addr(aL, wm*64 + mt*16, kb, lane));
                #pragma unroll
                for (int mt = 0; mt < 4; mt++)
                    #pragma unroll
                    for (int nt = 0; nt < 8; nt++)
                        mma16816(acc[mt][nt], af[mt], bf[nt]);
            }
        }
        if (ch < NCH-1)
            load_convert_A(smc, nxt_off, emb, rows_s, (ch + 1)*KB, t);
    }
    __syncthreads();   // everyone done computing; stage smem is now reusable

    // ---- epilogue part 1: acc -> smem x with +b1, ReLU ----
    float* XS = (float*)(smc + OFF_XS);
    {
        const int lr4 = lane >> 2, lc2 = (lane & 3)*2;
        #pragma unroll
        for (int mt = 0; mt < 4; mt++) {
            #pragma unroll
            for (int nt = 0; nt < 8; nt++) {
                int r0 = wm*64 + mt*16 + lr4;
                int c0 = wn*64 + nt*8 + lc2;
                float ba = b1s[c0], bb = b1s[c0+1];
                float2 v0 = make_float2(fmaxf(acc[mt][nt][0] + ba, 0.f),
                                        fmaxf(acc[mt][nt][1] + bb, 0.f));
                float2 v1 = make_float2(fmaxf(acc[mt][nt][2] + ba, 0.f),
                                        fmaxf(acc[mt][nt][3] + bb, 0.f));
                *reinterpret_cast<float2*>(&XS[r0*XS_STRIDE + c0]) = v0;
                *reinterpret_cast<float2*>(&XS[(r0+8)*XS_STRIDE + c0]) = v1;
            }
        }
    }
    float* W2S  = (float*)(smc + OFF_W2S);
    float* HRED = (float*)(smc + OFF_HRED);
    for (int i = t; i < HID*CLS; i += 256) W2S[i] = W2[i];
    __syncthreads();

    // ---- epilogue part 2: h = x @ W2 (split over 2 halves of K) ----
    {
        const int row = t & 127, half = t >> 7;
        float hacc[CLS];
        #pragma unroll
        for (int c = 0; c < CLS; c++) hacc[c] = 0.f;
        const float* xr = XS + row*XS_STRIDE + half*128;
        #pragma unroll 4
        for (int n = 0; n < 128; n++) {
            float xv = xr[n];
            const float4* w4 = reinterpret_cast<const float4*>(
                W2S + (half*128 + n)*CLS);
            #pragma unroll
            for (int q = 0; q < 5; q++) {
                float4 w = w4[q];
                hacc[q*4+0] = fmaf(xv, w.x, hacc[q*4+0]);
                hacc[q*4+1] = fmaf(xv, w.y, hacc[q*4+1]);
                hacc[q*4+2] = fmaf(xv, w.z, hacc[q*4+2]);
                hacc[q*4+3] = fmaf(xv, w.w, hacc[q*4+3]);
            }
        }
        float* hp = HRED + t*CLS;
        #pragma unroll
        for (int c = 0; c < CLS; c++) hp[c] = hacc[c];
    }
    __syncthreads();
    if (t < 128) {
        #pragma unroll
        for (int c = 0; c < CLS; c++)
            g_h[(m0 + t)*CLS + c] =
                HRED[t*CLS + c] + HRED[(128 + t)*CLS + c] + b2s[c];
    }
}

// ---------------- K3: per-head projection + attention logits -------------
#define WPAD 404
__global__ __launch_bounds__(256) void k_zscore(
    const float* __restrict__ gat_W, const float* __restrict__ a_src,
    const float* __restrict__ a_dst, int layer)
{
    __shared__ float Ws[HEADS*WPAD];
    __shared__ float as_s[HEADS*CLS], ad_s[HEADS*CLS];
    __shared__ float hs[32*CLS];
    const int t = threadIdx.x;
    const float* Wl = gat_W + layer*HEADS*CLS*CLS;
    for (int i = t; i < HEADS*CLS*CLS; i += 256) {
        int hd = i / (CLS*CLS), r = i % (CLS*CLS);
        Ws[hd*WPAD + r] = Wl[i];
    }
    for (int i = t; i < HEADS*CLS; i += 256) {
        as_s[i] = a_src[layer*HEADS*CLS + i];
        ad_s[i] = a_dst[layer*HEADS*CLS + i];
    }
    const int n0 = blockIdx.x * 32;
    for (int i = t; i < 32*CLS; i += 256) hs[i] = g_h[n0*CLS + i];
    __syncthreads();

    const int hd = t & 7, ni = t >> 3;
    const int n = n0 + ni;
    const float* hrow = hs + ni*CLS;
    const float* W = Ws + hd*WPAD;
    float zrow[CLS];
    #pragma unroll
    for (int c = 0; c < CLS; c++) zrow[c] = 0.f;
    #pragma unroll
    for (int c2 = 0; c2 < CLS; c2++) {
        float hv = hrow[c2];
        #pragma unroll
        for (int c = 0; c < CLS; c++)
            zrow[c] = fmaf(hv, W[c2*CLS + c], zrow[c]);
    }
    float es = 0.f, ed = 0.f;
    #pragma unroll
    for (int c = 0; c < CLS; c++) {
        es = fmaf(zrow[c], as_s[hd*CLS + c], es);
        ed = fmaf(zrow[c], ad_s[hd*CLS + c], ed);
    }
    float* zo = g_z + ((size_t)hd*NNODES + n)*CLS;
    #pragma unroll
    for (int c = 0; c < CLS; c++) zo[c] = zrow[c];
    g_es[n*HEADS + hd] = es;
    g_ed[n*HEADS + hd] = ed;
}

// ---------------- K4: banded edge softmax ----------------
__global__ __launch_bounds__(256) void k_att()
{
    int idx = blockIdx.x*256 + threadIdx.x;   // HEADS*NNODES
    int hd = idx / NNODES, n = idx % NNODES;
    int pos = n % LSEQ;
    int base = n - pos;
    float ed = g_ed[n*HEADS + hd];
    float e[WIN];
    float m = -1e30f;
    #pragma unroll
    for (int w = 0; w < WIN; w++) {
        int j = pos - NGW + w;
        bool valid = (j >= 0) & (j < LSEQ);
        int jj = valid ? j : pos;
        float ev = g_es[(base + jj)*HEADS + hd] + ed;
        ev = ev > 0.f ? ev : 0.2f*ev;
        e[w] = valid ? ev : -1e30f;
        m = fmaxf(m, e[w]);
    }
    float ex[WIN], s = 0.f;
    #pragma unroll
    for (int w = 0; w < WIN; w++) {
        ex[w] = (e[w] > -1e29f) ? expf(e[w] - m) : 0.f;
        s += ex[w];
    }
    float inv = 1.f / (s + 1e-9f);
    #pragma unroll
    for (int w = 0; w < WIN; w++) g_att[(size_t)idx*WIN + w] = ex[w]*inv;
}

// ---------------- K5: fused 3-hop diffusion in smem ----------------
#define DIFF_SMEM ((7000*3 + 2450) * 4)   // 93800 bytes
__global__ __launch_bounds__(256) void k_diffuse_fused()
{
    extern __shared__ float ds[];
    float* z0 = ds;
    float* zA = ds + 7000;
    float* zB = ds + 14000;
    float* at = ds + 21000;
    const int t = threadIdx.x;
    const int hd = blockIdx.x & 7, doc = blockIdx.x >> 3;

    const float* zg = g_z + ((size_t)hd*NNODES + doc*LSEQ)*CLS;
    for (int i = t; i < 1750; i += 256)
        reinterpret_cast<float4*>(z0)[i] = reinterpret_cast<const float4*>(zg)[i];
    const float* ag = g_att + ((size_t)hd*NNODES + doc*LSEQ)*WIN;
    for (int i = t; i < 2450; i += 256) at[i] = ag[i];
    __syncthreads();

    #pragma unroll
    for (int hop = 0; hop < KHOPS; hop++) {
        const float* zin  = (hop == 0) ? z0 : ((hop == 1) ? zB : zA);
        float*       zout = (hop == 1) ? zA : zB;
        for (int i = t; i < LSEQ*CLS; i += 256) {
            int p = i / CLS, c = i - p*CLS;
            const float* a = at + p*WIN;
            float acc = 0.f;
            #pragma unroll
            for (int w = 0; w < WIN; w++) {
                int pp = p - NGW + w;
                pp = pp < 0 ? 0 : (pp >= LSEQ ? LSEQ-1 : pp);
                acc = fmaf(a[w], zin[pp*CLS + c], acc);
            }
            zout[i] = (1.f - ALPHA)*acc + ALPHA*z0[i];
        }
        __syncthreads();
    }
    float* zo = g_zt + ((size_t)hd*NNODES + doc*LSEQ)*CLS;
    for (int i = t; i < 1750; i += 256)
        reinterpret_cast<float4*>(zo)[i] = reinterpret_cast<const float4*>(zB)[i];
}

// ---------------- K6: ELU + mean over heads ----------------
__global__ __launch_bounds__(256) void k_merge()
{
    int idx = blockIdx.x*256 + threadIdx.x;   // NNODES*CLS
    float acc = 0.f;
    #pragma unroll
    for (int hd = 0; hd < HEADS; hd++) {
        float v = g_zt[(size_t)hd*NNODES*CLS + idx];
        acc += (v > 0.f) ? v : expm1f(v);
    }
    g_h[idx] = acc * (1.f / HEADS);
}

// ---------------- K7: gated readout ----------------
__global__ __launch_bounds__(256) void k_readout(
    const float* __restrict__ w_gate, const float* __restrict__ b_gate,
    float* __restrict__ out)
{
    __shared__ float wg[CLS];
    __shared__ float sred[240];
    const int t = threadIdx.x;
    if (t < CLS) wg[t] = w_gate[t];
    __syncthreads();
    const int doc = blockIdx.x;
    const float bg = b_gate[0];
    float acc = 0.f;
    if (t < 240) {
        int c = t % CLS, r = t / CLS;
        for (int p = r; p < LSEQ; p += 12) {
            const float* hr = g_h + (doc*LSEQ + p)*CLS;
            float dot = bg;
            #pragma unroll
            for (int k = 0; k < CLS; k++) dot = fmaf(hr[k], wg[k], dot);
            float gate = 1.f / (1.f + expf(-dot));
            acc = fmaf(gate, hr[c], acc);
        }
        sred[t] = acc;
    }
    __syncthreads();
    if (t < CLS) {
        float s = 0.f;
        #pragma unroll
        for (int r = 0; r < 12; r++) s += sred[r*CLS + t];
        out[doc*CLS + t] = s;
    }
}

// ---------------- launch ----------------
extern "C" void kernel_launch(void* const* d_in, const int* in_sizes, int n_in,
                              void* d_out, int out_size)
{
    const int*   node_ids = (const int*)  d_in[0];
    const float* emb    = (const float*) d_in[4];
    const float* W1     = (const float*) d_in[5];
    const float* b1     = (const float*) d_in[6];
    const float* W2     = (const float*) d_in[7];
    const float* b2     = (const float*) d_in[8];
    const float* gat_W  = (const float*) d_in[9];
    const float* a_src  = (const float*) d_in[10];
    const float* a_dst  = (const float*) d_in[11];
    const float* w_gate = (const float*) d_in[12];
    const float* b_gate = (const float*) d_in[13];
    float* out = (float*)d_out;

    cudaFuncSetAttribute(k_gemm1tc,
        cudaFuncAttributeMaxDynamicSharedMemorySize, GEMM_SMEM);
    cudaFuncSetAttribute(k_diffuse_fused,
        cudaFuncAttributeMaxDynamicSharedMemorySize, DIFF_SMEM);

    k_prepw<<<HID*DIM/256, 256>>>(W1);                                    // 768
    k_gemm1tc<<<NNODES/128, 256, GEMM_SMEM>>>(node_ids, emb, b1, W2, b2); // 350
    for (int l = 0; l < LAYERS; l++) {
        k_zscore<<<NNODES/32, 256>>>(gat_W, a_src, a_dst, l);       // 1400
        k_att<<<NNODES*HEADS/256, 256>>>();                         // 1400
        k_diffuse_fused<<<B_DOCS*HEADS, 256, DIFF_SMEM>>>();        // 1024
        k_merge<<<NNODES*CLS/256, 256>>>();                         // 3500
    }
    k_readout<<<B_DOCS, 256>>>(w_gate, b_gate, out);
}

// round 4
// speedup vs baseline: 2.5820x; 1.4207x over previous
#include <cuda_runtime.h>
#include <cuda_bf16.h>
#include <math.h>
#include <stdint.h>

// ---------------- problem constants ----------------
#define VOCAB   50000
#define B_DOCS  128
#define LSEQ    350
#define NGW     3
#define DIM     768
#define HID     256
#define CLS     20
#define HEADS   8
#define LAYERS  2
#define KHOPS   3
#define ALPHA   0.15f
#define NNODES  (B_DOCS*LSEQ)      // 44800
#define WIN     7

// ---------------- scratch ----------------
__device__ float g_h  [NNODES*CLS];                    // node features
__device__ float g_zt [(size_t)HEADS*NNODES*CLS];      // diffusion result
__device__ __nv_bfloat16 g_Wth[HID*DIM];               // W1^T hi  [256,768]
__device__ __nv_bfloat16 g_Wtl[HID*DIM];               // W1^T lo

// ---------------- helpers ----------------
__device__ __forceinline__ uint32_t smem_u32(const void* p) {
    uint32_t a;
    asm("{ .reg .u64 t; cvta.to.shared.u64 t, %1; cvt.u32.u64 %0, t; }"
        : "=r"(a) : "l"(p));
    return a;
}
#define SWZ64(o) ((o) ^ (((o) >> 3) & 0x30))

__device__ __forceinline__ void ldsm4(uint32_t* r, uint32_t addr) {
    asm volatile("ldmatrix.sync.aligned.m8n8.x4.shared.b16 {%0,%1,%2,%3}, [%4];"
        : "=r"(r[0]), "=r"(r[1]), "=r"(r[2]), "=r"(r[3]) : "r"(addr));
}
__device__ __forceinline__ void mma16816(float* c, const uint32_t* a, const uint32_t* b) {
    asm volatile("mma.sync.aligned.m16n8k16.row.col.f32.bf16.bf16.f32 "
        "{%0,%1,%2,%3}, {%4,%5,%6,%7}, {%8,%9}, {%0,%1,%2,%3};"
        : "+f"(c[0]), "+f"(c[1]), "+f"(c[2]), "+f"(c[3])
        : "r"(a[0]), "r"(a[1]), "r"(a[2]), "r"(a[3]), "r"(b[0]), "r"(b[1]));
}
__device__ __forceinline__ void cpasync16(uint32_t dst, const void* src) {
    size_t gs = __cvta_generic_to_global(src);
    asm volatile("cp.async.cg.shared.global [%0], [%1], 16;"
                 :: "r"(dst), "l"(gs) : "memory");
}
#define CP_COMMIT() asm volatile("cp.async.commit_group;" ::: "memory")
#define CP_WAIT0()  asm volatile("cp.async.wait_group 0;" ::: "memory")
#define CP_WAIT1()  asm volatile("cp.async.wait_group 1;" ::: "memory")

// ---------------- K0: coalesced transpose+split of W1 -> bf16 hi/lo ------
__global__ __launch_bounds__(256) void k_prepw(const float* __restrict__ W1)
{
    __shared__ float tile[32][33];
    const int k0 = blockIdx.x * 32;    // over DIM (24)
    const int n0 = blockIdx.y * 32;    // over HID (8)
    const int tx = threadIdx.x, ty = threadIdx.y;  // 32 x 8
    #pragma unroll
    for (int i = 0; i < 4; i++)
        tile[ty + i*8][tx] = W1[(k0 + ty + i*8)*HID + n0 + tx];
    __syncthreads();
    #pragma unroll
    for (int i = 0; i < 4; i++) {
        int n = n0 + ty + i*8;
        float v = tile[tx][ty + i*8];
        __nv_bfloat16 h = __float2bfloat16_rn(v);
        g_Wth[(size_t)n*DIM + k0 + tx] = h;
        g_Wtl[(size_t)n*DIM + k0 + tx] =
            __float2bfloat16_rn(v - __bfloat162float(h));
    }
}

// ---------------- K1: gather + GEMM1(bf16 3-pass mma) + GEMM2 fused ------
#define TM       160
#define KB       32
#define NCH      (DIM/KB)        // 24
#define OFF_ROWS 0               // 160 * 4
#define OFF_B1   768             // 256 * 4
#define OFF_B2   1792            // 20 * 4 (+pad)
#define OFF_AS   2048            // Asplit: 2 x 20480 (H 10240 | L 10240)
#define ASP_L    10240
#define OFF_AR   43008           // Araw: 2 x 20480
#define OFF_BB   83968           // B: 2 x 32768 (H 16384 | L 16384)
#define BB_L     16384
#define XS_STRIDE 259
#define OFF_XS   2048            // 160*259*4 = 165760 -> 167808
#define OFF_W2S  167808          // 20480 -> 188288
#define OFF_HRED 188288          // 320*20*4 = 25600 -> 213888
#define GEMM_SMEM 213888

__device__ __forceinline__ uint32_t a_addr64(uint32_t base, int row0, int kb, int lane) {
    int q = lane >> 3, lr = lane & 7;
    int row = row0 + ((q & 1) << 3) + lr;
    int k   = kb + ((q >> 1) << 3);
    return base + SWZ64((uint32_t)(row*64 + k*2));
}
__device__ __forceinline__ uint32_t b_addr64(uint32_t base, int n0, int kb, int lane) {
    int q = lane >> 3, lr = lane & 7;
    int n = n0 + ((q >> 1) << 3) + lr;
    int k = kb + ((q & 1) << 3);
    return base + SWZ64((uint32_t)(n*64 + k*2));
}

__device__ __forceinline__ void issue_chunk(
    uint32_t sb, const float* __restrict__ emb, const int* rows_s, int ch, int t)
{
    const int buf = ch & 1;
    const int k0 = ch * KB;
    const uint32_t bdst = sb + OFF_BB + buf*32768;
    #pragma unroll
    for (int i = 0; i < 4; i++) {
        int idx = t + i*256;               // 1024 = 256n x 4c
        int n = idx >> 2, c = idx & 3;
        uint32_t so = SWZ64((uint32_t)(n*64 + c*16));
        cpasync16(bdst + so,          g_Wth + (size_t)n*DIM + k0 + c*8);
        cpasync16(bdst + BB_L + so,   g_Wtl + (size_t)n*DIM + k0 + c*8);
    }
    const uint32_t adst = sb + OFF_AR + buf*20480;
    #pragma unroll
    for (int i = 0; i < 5; i++) {
        int idx = t + i*256;               // 1280 = 160m x 8c
        int m = idx >> 3, c = idx & 7;
        cpasync16(adst + (uint32_t)(m*128 + c*16),
                  emb + (size_t)rows_s[m]*DIM + k0 + c*4);
    }
}

__device__ __forceinline__ void convert_chunk(char* smc, int ch, int t)
{
    const int buf = ch & 1;
    const char* raw = smc + OFF_AR + buf*20480;
    char* dH = smc + OFF_AS + buf*20480;
    char* dL = dH + ASP_L;
    #pragma unroll
    for (int i = 0; i < 5; i++) {
        int idx = t + i*256;
        int m = idx >> 3, g = idx & 7;
        float4 v = *reinterpret_cast<const float4*>(raw + m*128 + g*16);
        __nv_bfloat162 h0 = __float22bfloat162_rn(make_float2(v.x, v.y));
        __nv_bfloat162 h1 = __float22bfloat162_rn(make_float2(v.z, v.w));
        float2 f0 = __bfloat1622float2(h0);
        float2 f1 = __bfloat1622float2(h1);
        __nv_bfloat162 l0 = __float22bfloat162_rn(make_float2(v.x-f0.x, v.y-f0.y));
        __nv_bfloat162 l1 = __float22bfloat162_rn(make_float2(v.z-f1.x, v.w-f1.y));
        uint32_t so = SWZ64((uint32_t)(m*64 + g*8));
        uint2 hv, lv;
        hv.x = *reinterpret_cast<uint32_t*>(&h0);
        hv.y = *reinterpret_cast<uint32_t*>(&h1);
        lv.x = *reinterpret_cast<uint32_t*>(&l0);
        lv.y = *reinterpret_cast<uint32_t*>(&l1);
        *reinterpret_cast<uint2*>(dH + so) = hv;
        *reinterpret_cast<uint2*>(dL + so) = lv;
    }
}

__global__ __launch_bounds__(256, 1) void k_gemm1tc(
    const int* __restrict__ node_ids, const float* __restrict__ emb,
    const float* __restrict__ b1, const float* __restrict__ W2,
    const float* __restrict__ b2)
{
    extern __shared__ char smc[];
    const uint32_t sb = smem_u32(smc);
    const int t = threadIdx.x, lane = t & 31, wid = t >> 5;
    const int wm = wid >> 2, wn = wid & 3;       // 2 x 4 warps
    const int m0 = blockIdx.x * TM;
    int*   rows_s = (int*)(smc + OFF_ROWS);
    float* b1s    = (float*)(smc + OFF_B1);
    float* b2s    = (float*)(smc + OFF_B2);

    if (t < TM) rows_s[t] = node_ids[m0 + t];
    b1s[t] = b1[t];
    if (t < CLS) b2s[t] = b2[t];
    __syncthreads();

    float acc[5][8][4];
    #pragma unroll
    for (int mt = 0; mt < 5; mt++)
        #pragma unroll
        for (int nt = 0; nt < 8; nt++)
            #pragma unroll
            for (int q = 0; q < 4; q++) acc[mt][nt][q] = 0.f;

    // prologue: stage chunks 0 and 1
    issue_chunk(sb, emb, rows_s, 0, t); CP_COMMIT();
    issue_chunk(sb, emb, rows_s, 1, t); CP_COMMIT();
    CP_WAIT1();
    __syncthreads();
    convert_chunk(smc, 0, t);
    __syncthreads();

    for (int ch = 0; ch < NCH; ch++) {
        const int buf = ch & 1;
        const uint32_t aH = sb + OFF_AS + buf*20480;
        const uint32_t aL = aH + ASP_L;
        const uint32_t bH = sb + OFF_BB + buf*32768;
        const uint32_t bL = bH + BB_L;
        // ---- compute chunk ch ----
        #pragma unroll
        for (int ks = 0; ks < 2; ks++) {
            const int kb = ks*16;
            uint32_t af[5][4], bf[8][2], cf[8][2];
            #pragma unroll
            for (int mt = 0; mt < 5; mt++)
                ldsm4(af[mt], a_addr64(aH, wm*80 + mt*16, kb, lane));
            #pragma unroll
            for (int p = 0; p < 4; p++) {
                uint32_t r[4];
                ldsm4(r, b_addr64(bH, wn*64 + p*16, kb, lane));
                bf[p*2][0]=r[0]; bf[p*2][1]=r[1];
                bf[p*2+1][0]=r[2]; bf[p*2+1][1]=r[3];
            }
            #pragma unroll
            for (int mt = 0; mt < 5; mt++)
                #pragma unroll
                for (int nt = 0; nt < 8; nt++)
                    mma16816(acc[mt][nt], af[mt], bf[nt]);
            #pragma unroll
            for (int p = 0; p < 4; p++) {
                uint32_t r[4];
                ldsm4(r, b_addr64(bL, wn*64 + p*16, kb, lane));
                cf[p*2][0]=r[0]; cf[p*2][1]=r[1];
                cf[p*2+1][0]=r[2]; cf[p*2+1][1]=r[3];
            }
            #pragma unroll
            for (int mt = 0; mt < 5; mt++)
                #pragma unroll
                for (int nt = 0; nt < 8; nt++)
                    mma16816(acc[mt][nt], af[mt], cf[nt]);
            #pragma unroll
            for (int mt = 0; mt < 5; mt++)
                ldsm4(af[mt], a_addr64(aL, wm*80 + mt*16, kb, lane));
            #pragma unroll
            for (int mt = 0; mt < 5; mt++)
                #pragma unroll
                for (int nt = 0; nt < 8; nt++)
                    mma16816(acc[mt][nt], af[mt], bf[nt]);
        }
        __syncthreads();                         // all reads of buf done
        if (ch + 2 < NCH) { issue_chunk(sb, emb, rows_s, ch + 2, t); CP_COMMIT(); }
        if (ch + 1 < NCH) {
            if (ch + 2 < NCH) CP_WAIT1(); else CP_WAIT0();
            __syncthreads();
            convert_chunk(smc, ch + 1, t);
            __syncthreads();
        }
    }
    __syncthreads();

    // ---- epilogue 1: acc -> XS with +b1, ReLU ----
    float* XS = (float*)(smc + OFF_XS);
    {
        const int lr4 = lane >> 2, lc2 = (lane & 3)*2;
        #pragma unroll
        for (int mt = 0; mt < 5; mt++) {
            #pragma unroll
            for (int nt = 0; nt < 8; nt++) {
                int r0 = wm*80 + mt*16 + lr4;
                int c0 = wn*64 + nt*8 + lc2;
                float ba = b1s[c0], bb = b1s[c0+1];
                XS[r0*XS_STRIDE + c0]       = fmaxf(acc[mt][nt][0] + ba, 0.f);
                XS[r0*XS_STRIDE + c0 + 1]   = fmaxf(acc[mt][nt][1] + bb, 0.f);
                XS[(r0+8)*XS_STRIDE + c0]   = fmaxf(acc[mt][nt][2] + ba, 0.f);
                XS[(r0+8)*XS_STRIDE + c0+1] = fmaxf(acc[mt][nt][3] + bb, 0.f);
            }
        }
    }
    float* W2S  = (float*)(smc + OFF_W2S);
    float* HRED = (float*)(smc + OFF_HRED);
    for (int i = t; i < HID*CLS; i += 256) W2S[i] = W2[i];
    __syncthreads();

    // ---- epilogue 2: h = relu(x) @ W2, (row, K-half) split over 320 workers
    for (int p = t; p < 2*TM; p += 256) {
        int half = p / TM, row = p - half*TM;
        float hacc[CLS];
        #pragma unroll
        for (int c = 0; c < CLS; c++) hacc[c] = 0.f;
        const float* xr = XS + row*XS_STRIDE + half*128;
        #pragma unroll 4
        for (int n = 0; n < 128; n++) {
            float xv = xr[n];
            const float4* w4 = reinterpret_cast<const float4*>(
                W2S + (half*128 + n)*CLS);
            #pragma unroll
            for (int q = 0; q < 5; q++) {
                float4 w = w4[q];
                hacc[q*4+0] = fmaf(xv, w.x, hacc[q*4+0]);
                hacc[q*4+1] = fmaf(xv, w.y, hacc[q*4+1]);
                hacc[q*4+2] = fmaf(xv, w.z, hacc[q*4+2]);
                hacc[q*4+3] = fmaf(xv, w.w, hacc[q*4+3]);
            }
        }
        #pragma unroll
        for (int c = 0; c < CLS; c++) HRED[p*CLS + c] = hacc[c];
    }
    __syncthreads();
    if (t < TM) {
        #pragma unroll
        for (int c = 0; c < CLS; c++)
            g_h[(m0 + t)*CLS + c] =
                HRED[t*CLS + c] + HRED[(TM + t)*CLS + c] + b2s[c];
    }
}

// ---------------- K2: fused GAT layer (proj + att softmax + 3 hops) ------
// block = (doc, head); everything resident in shared memory
#define GAT_SMEM (24608*4)   // 98432 bytes
__global__ __launch_bounds__(256) void k_gat(
    const float* __restrict__ gat_W, const float* __restrict__ a_src,
    const float* __restrict__ a_dst, int layer)
{
    extern __shared__ float gs[];
    float* hb   = gs;           // 7000: h, later reused as zA
    float* z0b  = gs + 7000;    // 7000
    float* zBb  = gs + 14000;   // 7000
    float* attb = gs + 21000;   // 2464
    float* esb  = gs + 23464;   // 352
    float* edb  = gs + 23816;   // 352
    float* Wb   = gs + 24168;   // 400
    float* asb  = gs + 24568;   // 20
    float* adb  = gs + 24588;   // 20
    const int t = threadIdx.x;
    const int hd = blockIdx.x & 7, doc = blockIdx.x >> 3;

    const float4* hg = reinterpret_cast<const float4*>(g_h + (size_t)doc*LSEQ*CLS);
    for (int i = t; i < LSEQ*CLS/4; i += 256)
        reinterpret_cast<float4*>(hb)[i] = hg[i];
    const float* Wg = gat_W + ((size_t)layer*HEADS + hd)*CLS*CLS;
    for (int i = t; i < CLS*CLS; i += 256) Wb[i] = Wg[i];
    if (t < CLS) {
        asb[t] = a_src[(layer*HEADS + hd)*CLS + t];
        adb[t] = a_dst[(layer*HEADS + hd)*CLS + t];
    }
    __syncthreads();

    // z projection + attention scores
    for (int p = t; p < LSEQ; p += 256) {
        float zr[CLS];
        #pragma unroll
        for (int c = 0; c < CLS; c++) zr[c] = 0.f;
        const float* hr = hb + p*CLS;
        #pragma unroll
        for (int c2 = 0; c2 < CLS; c2++) {
            float hv = hr[c2];
            #pragma unroll
            for (int c = 0; c < CLS; c++)
                zr[c] = fmaf(hv, Wb[c2*CLS + c], zr[c]);
        }
        float es = 0.f, ed = 0.f;
        #pragma unroll
        for (int c = 0; c < CLS; c++) {
            es = fmaf(zr[c], asb[c], es);
            ed = fmaf(zr[c], adb[c], ed);
        }
        esb[p] = es; edb[p] = ed;
        #pragma unroll
        for (int c = 0; c < CLS; c++) z0b[p*CLS + c] = zr[c];
    }
    __syncthreads();

    // banded softmax over incoming window
    for (int p = t; p < LSEQ; p += 256) {
        float ed = edb[p];
        float e[WIN], m = -1e30f;
        #pragma unroll
        for (int w = 0; w < WIN; w++) {
            int j = p - NGW + w;
            bool valid = (j >= 0) & (j < LSEQ);
            int jj = valid ? j : p;
            float ev = esb[jj] + ed;
            ev = ev > 0.f ? ev : 0.2f*ev;
            e[w] = valid ? ev : -1e30f;
            m = fmaxf(m, e[w]);
        }
        float ex[WIN], s = 0.f;
        #pragma unroll
        for (int w = 0; w < WIN; w++) {
            ex[w] = (e[w] > -1e29f) ? expf(e[w] - m) : 0.f;
            s += ex[w];
        }
        float inv = 1.f / (s + 1e-9f);
        #pragma unroll
        for (int w = 0; w < WIN; w++) attb[p*WIN + w] = ex[w]*inv;
    }
    __syncthreads();

    // hop 1: z0 -> hb(zA);  hop 2: hb -> zB;  hop 3: zB -> gmem
    #pragma unroll
    for (int hop = 0; hop < KHOPS; hop++) {
        const float* zin  = (hop == 0) ? z0b : ((hop == 1) ? hb : zBb);
        float*       zout = (hop == 0) ? hb  : zBb;
        float* zg = g_zt + ((size_t)hd*NNODES + doc*LSEQ)*CLS;
        for (int i = t; i < LSEQ*CLS; i += 256) {
            int p = i / CLS;
            int c = i - p*CLS;
            const float* a = attb + p*WIN;
            float acc = 0.f;
            #pragma unroll
            for (int w = 0; w < WIN; w++) {
                int pp = p - NGW + w;
                pp = pp < 0 ? 0 : (pp >= LSEQ ? LSEQ-1 : pp);
                acc = fmaf(a[w], zin[pp*CLS + c], acc);
            }
            float v = (1.f - ALPHA)*acc + ALPHA*z0b[i];
            if (hop == KHOPS-1) zg[i] = v;
            else zout[i] = v;
        }
        __syncthreads();
    }
}

// ---------------- K3: ELU + mean over heads ----------------
__global__ __launch_bounds__(256) void k_merge()
{
    int idx = blockIdx.x*256 + threadIdx.x;   // NNODES*CLS
    float acc = 0.f;
    #pragma unroll
    for (int hd = 0; hd < HEADS; hd++) {
        float v = g_zt[(size_t)hd*NNODES*CLS + idx];
        acc += (v > 0.f) ? v : expm1f(v);
    }
    g_h[idx] = acc * (1.f / HEADS);
}

// ---------------- K4: gated readout ----------------
__global__ __launch_bounds__(256) void k_readout(
    const float* __restrict__ w_gate, const float* __restrict__ b_gate,
    float* __restrict__ out)
{
    __shared__ float wg[CLS];
    __shared__ float sred[240];
    const int t = threadIdx.x;
    if (t < CLS) wg[t] = w_gate[t];
    __syncthreads();
    const int doc = blockIdx.x;
    const float bg = b_gate[0];
    float acc = 0.f;
    if (t < 240) {
        int c = t % CLS, r = t / CLS;
        for (int p = r; p < LSEQ; p += 12) {
            const float* hr = g_h + (doc*LSEQ + p)*CLS;
            float dot = bg;
            #pragma unroll
            for (int k = 0; k < CLS; k++) dot = fmaf(hr[k], wg[k], dot);
            float gate = 1.f / (1.f + expf(-dot));
            acc = fmaf(gate, hr[c], acc);
        }
        sred[t] = acc;
    }
    __syncthreads();
    if (t < CLS) {
        float s = 0.f;
        #pragma unroll
        for (int r = 0; r < 12; r++) s += sred[r*CLS + t];
        out[doc*CLS + t] = s;
    }
}

// ---------------- launch ----------------
extern "C" void kernel_launch(void* const* d_in, const int* in_sizes, int n_in,
                              void* d_out, int out_size)
{
    const int*   node_ids = (const int*)  d_in[0];
    const float* emb    = (const float*) d_in[4];
    const float* W1     = (const float*) d_in[5];
    const float* b1     = (const float*) d_in[6];
    const float* W2     = (const float*) d_in[7];
    const float* b2     = (const float*) d_in[8];
    const float* gat_W  = (const float*) d_in[9];
    const float* a_src  = (const float*) d_in[10];
    const float* a_dst  = (const float*) d_in[11];
    const float* w_gate = (const float*) d_in[12];
    const float* b_gate = (const float*) d_in[13];
    float* out = (float*)d_out;

    cudaFuncSetAttribute(k_gemm1tc,
        cudaFuncAttributeMaxDynamicSharedMemorySize, GEMM_SMEM);
    cudaFuncSetAttribute(k_gat,
        cudaFuncAttributeMaxDynamicSharedMemorySize, GAT_SMEM);

    k_prepw<<<dim3(DIM/32, HID/32), dim3(32, 8)>>>(W1);                  // 192
    k_gemm1tc<<<NNODES/TM, 256, GEMM_SMEM>>>(node_ids, emb, b1, W2, b2); // 280
    for (int l = 0; l < LAYERS; l++) {
        k_gat<<<B_DOCS*HEADS, 256, GAT_SMEM>>>(gat_W, a_src, a_dst, l);  // 1024
        k_merge<<<NNODES*CLS/256, 256>>>();                              // 3500
    }
    k_readout<<<B_DOCS, 256>>>(w_gate, b_gate, out);
}

// round 5
// speedup vs baseline: 2.9095x; 1.1268x over previous
#include <cuda_runtime.h>
#include <cuda_fp16.h>
#include <math.h>
#include <stdint.h>

// ---------------- problem constants ----------------
#define VOCAB   50000
#define B_DOCS  128
#define LSEQ    350
#define NGW     3
#define DIM     768
#define HID     256
#define CLS     20
#define HEADS   8
#define LAYERS  2
#define KHOPS   3
#define ALPHA   0.15f
#define NNODES  (B_DOCS*LSEQ)      // 44800
#define WIN     7

// ---------------- scratch ----------------
__device__ float g_h [NNODES*CLS];     // node features (ping)
__device__ float g_hB[NNODES*CLS];     // node features (pong)
__device__ __half g_Wh[HID*DIM];       // W1^T fp16  [256,768]

// ---------------- helpers ----------------
__device__ __forceinline__ uint32_t smem_u32(const void* p) {
    uint32_t a;
    asm("{ .reg .u64 t; cvta.to.shared.u64 t, %1; cvt.u32.u64 %0, t; }"
        : "=r"(a) : "l"(p));
    return a;
}
#define SWZ64(o) ((o) ^ (((o) >> 3) & 0x30))

__device__ __forceinline__ void ldsm4(uint32_t* r, uint32_t addr) {
    asm volatile("ldmatrix.sync.aligned.m8n8.x4.shared.b16 {%0,%1,%2,%3}, [%4];"
        : "=r"(r[0]), "=r"(r[1]), "=r"(r[2]), "=r"(r[3]) : "r"(addr));
}
__device__ __forceinline__ void mma16816(float* c, const uint32_t* a, const uint32_t* b) {
    asm volatile("mma.sync.aligned.m16n8k16.row.col.f32.f16.f16.f32 "
        "{%0,%1,%2,%3}, {%4,%5,%6,%7}, {%8,%9}, {%0,%1,%2,%3};"
        : "+f"(c[0]), "+f"(c[1]), "+f"(c[2]), "+f"(c[3])
        : "r"(a[0]), "r"(a[1]), "r"(a[2]), "r"(a[3]), "r"(b[0]), "r"(b[1]));
}
__device__ __forceinline__ void cpasync16(uint32_t dst, const void* src) {
    size_t gs = __cvta_generic_to_global(src);
    asm volatile("cp.async.cg.shared.global [%0], [%1], 16;"
                 :: "r"(dst), "l"(gs) : "memory");
}
#define CP_COMMIT() asm volatile("cp.async.commit_group;" ::: "memory")
#define CP_WAIT0()  asm volatile("cp.async.wait_group 0;" ::: "memory")
#define CP_WAIT1()  asm volatile("cp.async.wait_group 1;" ::: "memory")

// ---------------- K0: coalesced transpose of W1 -> fp16 ----------------
__global__ __launch_bounds__(256) void k_prepw(const float* __restrict__ W1)
{
    __shared__ float tile[32][33];
    const int k0 = blockIdx.x * 32;    // over DIM (24)
    const int n0 = blockIdx.y * 32;    // over HID (8)
    const int tx = threadIdx.x, ty = threadIdx.y;  // 32 x 8
    #pragma unroll
    for (int i = 0; i < 4; i++)
        tile[ty + i*8][tx] = W1[(k0 + ty + i*8)*HID + n0 + tx];
    __syncthreads();
    #pragma unroll
    for (int i = 0; i < 4; i++) {
        int n = n0 + ty + i*8;
        g_Wh[(size_t)n*DIM + k0 + tx] = __float2half_rn(tile[tx][ty + i*8]);
    }
}

// ---------------- K1: gather + GEMM1(fp16 2-pass mma) + GEMM2 fused ------
#define TM       160
#define KB       32
#define NCH      (DIM/KB)        // 24
#define OFF_ROWS 0               // 160 * 4
#define OFF_B1   768             // 256 * 4
#define OFF_B2   1792            // 20 * 4 (+pad)
#define OFF_AS   2048            // Asplit: 2 x 20480 (H 10240 | L 10240)
#define ASP_L    10240
#define OFF_AR   43008           // Araw fp32: 2 x 20480
#define OFF_BB   83968           // B fp16: 2 x 16384
#define XS_STRIDE 259
#define OFF_XS   2048            // 160*259*4 = 165760 -> 167808
#define OFF_W2S  167808          // 20480 -> 188288
#define OFF_HRED 188288          // 320*20*4 = 25600 -> 213888
#define GEMM_SMEM 213888

__device__ __forceinline__ uint32_t a_addr64(uint32_t base, int row0, int kb, int lane) {
    int q = lane >> 3, lr = lane & 7;
    int row = row0 + ((q & 1) << 3) + lr;
    int k   = kb + ((q >> 1) << 3);
    return base + SWZ64((uint32_t)(row*64 + k*2));
}
__device__ __forceinline__ uint32_t b_addr64(uint32_t base, int n0, int kb, int lane) {
    int q = lane >> 3, lr = lane & 7;
    int n = n0 + ((q >> 1) << 3) + lr;
    int k = kb + ((q & 1) << 3);
    return base + SWZ64((uint32_t)(n*64 + k*2));
}

__device__ __forceinline__ void issue_chunk(
    uint32_t sb, const float* __restrict__ emb, const int* rows_s, int ch, int t)
{
    const int buf = ch & 1;
    const int k0 = ch * KB;
    const uint32_t bdst = sb + OFF_BB + buf*16384;
    #pragma unroll
    for (int i = 0; i < 4; i++) {
        int idx = t + i*256;               // 1024 = 256n x 4c
        int n = idx >> 2, c = idx & 3;
        cpasync16(bdst + SWZ64((uint32_t)(n*64 + c*16)),
                  g_Wh + (size_t)n*DIM + k0 + c*8);
    }
    const uint32_t adst = sb + OFF_AR + buf*20480;
    #pragma unroll
    for (int i = 0; i < 5; i++) {
        int idx = t + i*256;               // 1280 = 160m x 8c
        int m = idx >> 3, c = idx & 7;
        cpasync16(adst + (uint32_t)(m*128 + c*16),
                  emb + (size_t)rows_s[m]*DIM + k0 + c*4);
    }
}

__device__ __forceinline__ void convert_chunk(char* smc, int ch, int t)
{
    const int buf = ch & 1;
    const char* raw = smc + OFF_AR + buf*20480;
    char* dH = smc + OFF_AS + buf*20480;
    char* dL = dH + ASP_L;
    #pragma unroll
    for (int i = 0; i < 5; i++) {
        int idx = t + i*256;
        int m = idx >> 3, g = idx & 7;
        float4 v = *reinterpret_cast<const float4*>(raw + m*128 + g*16);
        __half2 h0 = __float22half2_rn(make_float2(v.x, v.y));
        __half2 h1 = __float22half2_rn(make_float2(v.z, v.w));
        float2 f0 = __half22float2(h0);
        float2 f1 = __half22float2(h1);
        __half2 l0 = __float22half2_rn(make_float2(v.x-f0.x, v.y-f0.y));
        __half2 l1 = __float22half2_rn(make_float2(v.z-f1.x, v.w-f1.y));
        uint32_t so = SWZ64((uint32_t)(m*64 + g*8));
        uint2 hv, lv;
        hv.x = *reinterpret_cast<uint32_t*>(&h0);
        hv.y = *reinterpret_cast<uint32_t*>(&h1);
        lv.x = *reinterpret_cast<uint32_t*>(&l0);
        lv.y = *reinterpret_cast<uint32_t*>(&l1);
        *reinterpret_cast<uint2*>(dH + so) = hv;
        *reinterpret_cast<uint2*>(dL + so) = lv;
    }
}

__global__ __launch_bounds__(256, 1) void k_gemm1tc(
    const int* __restrict__ node_ids, const float* __restrict__ emb,
    const float* __restrict__ b1, const float* __restrict__ W2,
    const float* __restrict__ b2)
{
    extern __shared__ char smc[];
    const uint32_t sb = smem_u32(smc);
    const int t = threadIdx.x, lane = t & 31, wid = t >> 5;
    const int wm = wid >> 2, wn = wid & 3;       // 2 x 4 warps
    const int m0 = blockIdx.x * TM;
    int*   rows_s = (int*)(smc + OFF_ROWS);
    float* b1s    = (float*)(smc + OFF_B1);
    float* b2s    = (float*)(smc + OFF_B2);

    if (t < TM) rows_s[t] = node_ids[m0 + t];
    b1s[t] = b1[t];
    if (t < CLS) b2s[t] = b2[t];
    __syncthreads();

    float acc[5][8][4];
    #pragma unroll
    for (int mt = 0; mt < 5; mt++)
        #pragma unroll
        for (int nt = 0; nt < 8; nt++)
            #pragma unroll
            for (int q = 0; q < 4; q++) acc[mt][nt][q] = 0.f;

    // prologue: stage chunks 0 and 1
    issue_chunk(sb, emb, rows_s, 0, t); CP_COMMIT();
    issue_chunk(sb, emb, rows_s, 1, t); CP_COMMIT();
    CP_WAIT1();
    __syncthreads();
    convert_chunk(smc, 0, t);
    __syncthreads();

    for (int ch = 0; ch < NCH; ch++) {
        const int buf = ch & 1;
        const uint32_t aH = sb + OFF_AS + buf*20480;
        const uint32_t aL = aH + ASP_L;
        const uint32_t bH = sb + OFF_BB + buf*16384;
        // ---- compute chunk ch (2 passes: ah*bh + al*bh) ----
        #pragma unroll
        for (int ks = 0; ks < 2; ks++) {
            const int kb = ks*16;
            uint32_t af[5][4], bf[8][2];
            #pragma unroll
            for (int mt = 0; mt < 5; mt++)
                ldsm4(af[mt], a_addr64(aH, wm*80 + mt*16, kb, lane));
            #pragma unroll
            for (int p = 0; p < 4; p++) {
                uint32_t r[4];
                ldsm4(r, b_addr64(bH, wn*64 + p*16, kb, lane));
                bf[p*2][0]=r[0]; bf[p*2][1]=r[1];
                bf[p*2+1][0]=r[2]; bf[p*2+1][1]=r[3];
            }
            #pragma unroll
            for (int mt = 0; mt < 5; mt++)
                #pragma unroll
                for (int nt = 0; nt < 8; nt++)
                    mma16816(acc[mt][nt], af[mt], bf[nt]);
            #pragma unroll
            for (int mt = 0; mt < 5; mt++)
                ldsm4(af[mt], a_addr64(aL, wm*80 + mt*16, kb, lane));
            #pragma unroll
            for (int mt = 0; mt < 5; mt++)
                #pragma unroll
                for (int nt = 0; nt < 8; nt++)
                    mma16816(acc[mt][nt], af[mt], bf[nt]);
        }
        __syncthreads();                         // all reads of buf done
        if (ch + 2 < NCH) { issue_chunk(sb, emb, rows_s, ch + 2, t); CP_COMMIT(); }
        if (ch + 1 < NCH) {
            if (ch + 2 < NCH) CP_WAIT1(); else CP_WAIT0();
            __syncthreads();
            convert_chunk(smc, ch + 1, t);
            __syncthreads();
        }
    }
    __syncthreads();

    // ---- epilogue 1: acc -> XS with +b1, ReLU ----
    float* XS = (float*)(smc + OFF_XS);
    {
        const int lr4 = lane >> 2, lc2 = (lane & 3)*2;
        #pragma unroll
        for (int mt = 0; mt < 5; mt++) {
            #pragma unroll
            for (int nt = 0; nt < 8; nt++) {
                int r0 = wm*80 + mt*16 + lr4;
                int c0 = wn*64 + nt*8 + lc2;
                float ba = b1s[c0], bb = b1s[c0+1];
                XS[r0*XS_STRIDE + c0]       = fmaxf(acc[mt][nt][0] + ba, 0.f);
                XS[r0*XS_STRIDE + c0 + 1]   = fmaxf(acc[mt][nt][1] + bb, 0.f);
                XS[(r0+8)*XS_STRIDE + c0]   = fmaxf(acc[mt][nt][2] + ba, 0.f);
                XS[(r0+8)*XS_STRIDE + c0+1] = fmaxf(acc[mt][nt][3] + bb, 0.f);
            }
        }
    }
    float* W2S  = (float*)(smc + OFF_W2S);
    float* HRED = (float*)(smc + OFF_HRED);
    for (int i = t; i < HID*CLS; i += 256) W2S[i] = W2[i];
    __syncthreads();

    // ---- epilogue 2: h = relu(x) @ W2, (row, K-half) split over 320 workers
    for (int p = t; p < 2*TM; p += 256) {
        int half = p / TM, row = p - half*TM;
        float hacc[CLS];
        #pragma unroll
        for (int c = 0; c < CLS; c++) hacc[c] = 0.f;
        const float* xr = XS + row*XS_STRIDE + half*128;
        #pragma unroll 4
        for (int n = 0; n < 128; n++) {
            float xv = xr[n];
            const float4* w4 = reinterpret_cast<const float4*>(
                W2S + (half*128 + n)*CLS);
            #pragma unroll
            for (int q = 0; q < 5; q++) {
                float4 w = w4[q];
                hacc[q*4+0] = fmaf(xv, w.x, hacc[q*4+0]);
                hacc[q*4+1] = fmaf(xv, w.y, hacc[q*4+1]);
                hacc[q*4+2] = fmaf(xv, w.z, hacc[q*4+2]);
                hacc[q*4+3] = fmaf(xv, w.w, hacc[q*4+3]);
            }
        }
        #pragma unroll
        for (int c = 0; c < CLS; c++) HRED[p*CLS + c] = hacc[c];
    }
    __syncthreads();
    if (t < TM) {
        #pragma unroll
        for (int c = 0; c < CLS; c++)
            g_h[(m0 + t)*CLS + c] =
                HRED[t*CLS + c] + HRED[(TM + t)*CLS + c] + b2s[c];
    }
}

// ---------------- K2: zero a feature buffer ----------------
__global__ __launch_bounds__(256) void k_zero(int which)
{
    float* p = which ? g_hB : g_h;
    int i = blockIdx.x*256 + threadIdx.x;      // NNODES*CLS/4 = 224000
    reinterpret_cast<float4*>(p)[i] = make_float4(0.f, 0.f, 0.f, 0.f);
}

// ---------------- K3: fused GAT layer (proj+softmax+3 hops+ELU-mean) -----
// block = (doc, head); final hop atomically accumulates elu(v)/8 into dst
#define GAT_SMEM (24608*4)   // 98432 bytes
__global__ __launch_bounds__(256) void k_gat(
    const float* __restrict__ gat_W, const float* __restrict__ a_src,
    const float* __restrict__ a_dst, int layer)
{
    extern __shared__ float gs[];
    float* hb   = gs;           // 7000: h, later reused as zA
    float* z0b  = gs + 7000;    // 7000
    float* zBb  = gs + 14000;   // 7000
    float* attb = gs + 21000;   // 2464
    float* esb  = gs + 23464;   // 352
    float* edb  = gs + 23816;   // 352
    float* Wb   = gs + 24168;   // 400
    float* asb  = gs + 24568;   // 20
    float* adb  = gs + 24588;   // 20
    const int t = threadIdx.x;
    const int hd = blockIdx.x & 7, doc = blockIdx.x >> 3;
    const float* src = (layer == 0) ? g_h : g_hB;
    float*       dst = (layer == 0) ? g_hB : g_h;

    const float4* hg = reinterpret_cast<const float4*>(src + (size_t)doc*LSEQ*CLS);
    for (int i = t; i < LSEQ*CLS/4; i += 256)
        reinterpret_cast<float4*>(hb)[i] = hg[i];
    const float* Wg = gat_W + ((size_t)layer*HEADS + hd)*CLS*CLS;
    for (int i = t; i < CLS*CLS; i += 256) Wb[i] = Wg[i];
    if (t < CLS) {
        asb[t] = a_src[(layer*HEADS + hd)*CLS + t];
        adb[t] = a_dst[(layer*HEADS + hd)*CLS + t];
    }
    __syncthreads();

    // z projection + attention scores
    for (int p = t; p < LSEQ; p += 256) {
        float zr[CLS];
        #pragma unroll
        for (int c = 0; c < CLS; c++) zr[c] = 0.f;
        const float* hr = hb + p*CLS;
        #pragma unroll
        for (int c2 = 0; c2 < CLS; c2++) {
            float hv = hr[c2];
            #pragma unroll
            for (int c = 0; c < CLS; c++)
                zr[c] = fmaf(hv, Wb[c2*CLS + c], zr[c]);
        }
        float es = 0.f, ed = 0.f;
        #pragma unroll
        for (int c = 0; c < CLS; c++) {
            es = fmaf(zr[c], asb[c], es);
            ed = fmaf(zr[c], adb[c], ed);
        }
        esb[p] = es; edb[p] = ed;
        #pragma unroll
        for (int c = 0; c < CLS; c++) z0b[p*CLS + c] = zr[c];
    }
    __syncthreads();

    // banded softmax over incoming window
    for (int p = t; p < LSEQ; p += 256) {
        float ed = edb[p];
        float e[WIN], m = -1e30f;
        #pragma unroll
        for (int w = 0; w < WIN; w++) {
            int j = p - NGW + w;
            bool valid = (j >= 0) & (j < LSEQ);
            int jj = valid ? j : p;
            float ev = esb[jj] + ed;
            ev = ev > 0.f ? ev : 0.2f*ev;
            e[w] = valid ? ev : -1e30f;
            m = fmaxf(m, e[w]);
        }
        float ex[WIN], s = 0.f;
        #pragma unroll
        for (int w = 0; w < WIN; w++) {
            ex[w] = (e[w] > -1e29f) ? expf(e[w] - m) : 0.f;
            s += ex[w];
        }
        float inv = 1.f / (s + 1e-9f);
        #pragma unroll
        for (int w = 0; w < WIN; w++) attb[p*WIN + w] = ex[w]*inv;
    }
    __syncthreads();

    // hop 1: z0 -> hb(zA);  hop 2: hb -> zB;  hop 3: zB -> elu/8 atomics
    float* dsb = dst + (size_t)doc*LSEQ*CLS;
    #pragma unroll
    for (int hop = 0; hop < KHOPS; hop++) {
        const float* zin  = (hop == 0) ? z0b : ((hop == 1) ? hb : zBb);
        float*       zout = (hop == 0) ? hb  : zBb;
        for (int i = t; i < LSEQ*CLS; i += 256) {
            int p = i / CLS;
            int c = i - p*CLS;
            const float* a = attb + p*WIN;
            float acc = 0.f;
            #pragma unroll
            for (int w = 0; w < WIN; w++) {
                int pp = p - NGW + w;
                pp = pp < 0 ? 0 : (pp >= LSEQ ? LSEQ-1 : pp);
                acc = fmaf(a[w], zin[pp*CLS + c], acc);
            }
            float v = (1.f - ALPHA)*acc + ALPHA*z0b[i];
            if (hop == KHOPS-1) {
                float e = (v > 0.f) ? v : expm1f(v);
                atomicAdd(&dsb[i], e * (1.f/HEADS));
            } else {
                zout[i] = v;
            }
        }
        if (hop < KHOPS-1) __syncthreads();
    }
}

// ---------------- K4: gated readout ----------------
__global__ __launch_bounds__(256) void k_readout(
    const float* __restrict__ w_gate, const float* __restrict__ b_gate,
    float* __restrict__ out)
{
    __shared__ float wg[CLS];
    __shared__ float sred[240];
    const int t = threadIdx.x;
    if (t < CLS) wg[t] = w_gate[t];
    __syncthreads();
    const int doc = blockIdx.x;
    const float bg = b_gate[0];
    float acc = 0.f;
    if (t < 240) {
        int c = t % CLS, r = t / CLS;
        for (int p = r; p < LSEQ; p += 12) {
            const float* hr = g_h + (doc*LSEQ + p)*CLS;
            float dot = bg;
            #pragma unroll
            for (int k = 0; k < CLS; k++) dot = fmaf(hr[k], wg[k], dot);
            float gate = 1.f / (1.f + expf(-dot));
            acc = fmaf(gate, hr[c], acc);
        }
        sred[t] = acc;
    }
    __syncthreads();
    if (t < CLS) {
        float s = 0.f;
        #pragma unroll
        for (int r = 0; r < 12; r++) s += sred[r*CLS + t];
        out[doc*CLS + t] = s;
    }
}

// ---------------- launch ----------------
extern "C" void kernel_launch(void* const* d_in, const int* in_sizes, int n_in,
                              void* d_out, int out_size)
{
    const int*   node_ids = (const int*)  d_in[0];
    const float* emb    = (const float*) d_in[4];
    const float* W1     = (const float*) d_in[5];
    const float* b1     = (const float*) d_in[6];
    const float* W2     = (const float*) d_in[7];
    const float* b2     = (const float*) d_in[8];
    const float* gat_W  = (const float*) d_in[9];
    const float* a_src  = (const float*) d_in[10];
    const float* a_dst  = (const float*) d_in[11];
    const float* w_gate = (const float*) d_in[12];
    const float* b_gate = (const float*) d_in[13];
    float* out = (float*)d_out;

    cudaFuncSetAttribute(k_gemm1tc,
        cudaFuncAttributeMaxDynamicSharedMemorySize, GEMM_SMEM);
    cudaFuncSetAttribute(k_gat,
        cudaFuncAttributeMaxDynamicSharedMemorySize, GAT_SMEM);

    k_prepw<<<dim3(DIM/32, HID/32), dim3(32, 8)>>>(W1);                  // 192
    k_gemm1tc<<<NNODES/TM, 256, GEMM_SMEM>>>(node_ids, emb, b1, W2, b2); // 280
    for (int l = 0; l < LAYERS; l++) {
        k_zero<<<NNODES*CLS/1024, 256>>>(l == 0 ? 1 : 0);                // 875
        k_gat<<<B_DOCS*HEADS, 256, GAT_SMEM>>>(gat_W, a_src, a_dst, l);  // 1024
    }
    k_readout<<<B_DOCS, 256>>>(w_gate, b_gate, out);
}

// round 6
// speedup vs baseline: 3.2229x; 1.1077x over previous
#include <cuda_runtime.h>
#include <cuda_fp16.h>
#include <math.h>
#include <stdint.h>

// ---------------- problem constants ----------------
#define VOCAB   50000
#define B_DOCS  128
#define LSEQ    350
#define NGW     3
#define DIM     768
#define HID     256
#define CLS     20
#define HEADS   8
#define LAYERS  2
#define KHOPS   3
#define ALPHA   0.15f
#define NNODES  (B_DOCS*LSEQ)      // 44800
#define WIN     7

// ---------------- scratch ----------------
__device__ float g_h [NNODES*CLS];     // node features (ping)
__device__ float g_hB[NNODES*CLS];     // node features (pong)
__device__ __half g_Wh[HID*DIM];       // W1^T fp16  [256,768]

// ---------------- helpers ----------------
__device__ __forceinline__ uint32_t smem_u32(const void* p) {
    uint32_t a;
    asm("{ .reg .u64 t; cvta.to.shared.u64 t, %1; cvt.u32.u64 %0, t; }"
        : "=r"(a) : "l"(p));
    return a;
}
#define SWZ64(o) ((o) ^ (((o) >> 3) & 0x30))

__device__ __forceinline__ void ldsm4(uint32_t* r, uint32_t addr) {
    asm volatile("ldmatrix.sync.aligned.m8n8.x4.shared.b16 {%0,%1,%2,%3}, [%4];"
        : "=r"(r[0]), "=r"(r[1]), "=r"(r[2]), "=r"(r[3]) : "r"(addr));
}
__device__ __forceinline__ void mma16816(float* c, const uint32_t* a, const uint32_t* b) {
    asm volatile("mma.sync.aligned.m16n8k16.row.col.f32.f16.f16.f32 "
        "{%0,%1,%2,%3}, {%4,%5,%6,%7}, {%8,%9}, {%0,%1,%2,%3};"
        : "+f"(c[0]), "+f"(c[1]), "+f"(c[2]), "+f"(c[3])
        : "r"(a[0]), "r"(a[1]), "r"(a[2]), "r"(a[3]), "r"(b[0]), "r"(b[1]));
}
__device__ __forceinline__ void cpasync16(uint32_t dst, const void* src) {
    size_t gs = __cvta_generic_to_global(src);
    asm volatile("cp.async.cg.shared.global [%0], [%1], 16;"
                 :: "r"(dst), "l"(gs) : "memory");
}
#define CP_COMMIT() asm volatile("cp.async.commit_group;" ::: "memory")
#define CP_WAIT0()  asm volatile("cp.async.wait_group 0;" ::: "memory")
#define CP_WAIT1()  asm volatile("cp.async.wait_group 1;" ::: "memory")

// ---------------- K0: coalesced transpose of W1 -> fp16 ----------------
__global__ __launch_bounds__(256) void k_prepw(const float* __restrict__ W1)
{
    __shared__ float tile[32][33];
    const int k0 = blockIdx.x * 32;    // over DIM (24)
    const int n0 = blockIdx.y * 32;    // over HID (8)
    const int tx = threadIdx.x, ty = threadIdx.y;  // 32 x 8
    #pragma unroll
    for (int i = 0; i < 4; i++)
        tile[ty + i*8][tx] = W1[(k0 + ty + i*8)*HID + n0 + tx];
    __syncthreads();
    #pragma unroll
    for (int i = 0; i < 4; i++) {
        int n = n0 + ty + i*8;
        g_Wh[(size_t)n*DIM + k0 + tx] = __float2half_rn(tile[tx][ty + i*8]);
    }
}

// ---------------- K1: gather + GEMM1(fp16 1-pass mma) + GEMM2 fused ------
#define TM       160
#define KB       32
#define NCH      (DIM/KB)        // 24
#define OFF_ROWS 0               // 160 * 4
#define OFF_B1   768             // 256 * 4
#define OFF_B2   1792            // 20 * 4 (+pad)
#define OFF_AS   2048            // A fp16: 2 x 10240
#define OFF_AR   22528           // Araw fp32: 2 x 20480
#define OFF_BB   63488           // B fp16: 2 x 16384
#define XS_STRIDE 259
#define OFF_XS   2048            // 160*259*4 = 165760 -> 167808
#define OFF_W2S  167808          // 20480 -> 188288
#define OFF_HRED 188288          // 320*20*4 = 25600 -> 213888
#define GEMM_SMEM 213888

__device__ __forceinline__ uint32_t a_addr64(uint32_t base, int row0, int kb, int lane) {
    int q = lane >> 3, lr = lane & 7;
    int row = row0 + ((q & 1) << 3) + lr;
    int k   = kb + ((q >> 1) << 3);
    return base + SWZ64((uint32_t)(row*64 + k*2));
}
__device__ __forceinline__ uint32_t b_addr64(uint32_t base, int n0, int kb, int lane) {
    int q = lane >> 3, lr = lane & 7;
    int n = n0 + ((q >> 1) << 3) + lr;
    int k = kb + ((q & 1) << 3);
    return base + SWZ64((uint32_t)(n*64 + k*2));
}

__device__ __forceinline__ void issue_chunk(
    uint32_t sb, const float* __restrict__ emb, const int* rows_s, int ch, int t)
{
    const int buf = ch & 1;
    const int k0 = ch * KB;
    const uint32_t bdst = sb + OFF_BB + buf*16384;
    #pragma unroll
    for (int i = 0; i < 4; i++) {
        int idx = t + i*256;               // 1024 = 256n x 4c
        int n = idx >> 2, c = idx & 3;
        cpasync16(bdst + SWZ64((uint32_t)(n*64 + c*16)),
                  g_Wh + (size_t)n*DIM + k0 + c*8);
    }
    const uint32_t adst = sb + OFF_AR + buf*20480;
    #pragma unroll
    for (int i = 0; i < 5; i++) {
        int idx = t + i*256;               // 1280 = 160m x 8c
        int m = idx >> 3, c = idx & 7;
        cpasync16(adst + (uint32_t)(m*128 + c*16),
                  emb + (size_t)rows_s[m]*DIM + k0 + c*4);
    }
}

__device__ __forceinline__ void convert_chunk(char* smc, int ch, int t)
{
    const int buf = ch & 1;
    const char* raw = smc + OFF_AR + buf*20480;
    char* dH = smc + OFF_AS + buf*10240;
    #pragma unroll
    for (int i = 0; i < 5; i++) {
        int idx = t + i*256;
        int m = idx >> 3, g = idx & 7;
        float4 v = *reinterpret_cast<const float4*>(raw + m*128 + g*16);
        __half2 h0 = __float22half2_rn(make_float2(v.x, v.y));
        __half2 h1 = __float22half2_rn(make_float2(v.z, v.w));
        uint2 hv;
        hv.x = *reinterpret_cast<uint32_t*>(&h0);
        hv.y = *reinterpret_cast<uint32_t*>(&h1);
        *reinterpret_cast<uint2*>(dH + SWZ64((uint32_t)(m*64 + g*8))) = hv;
    }
}

__global__ __launch_bounds__(256, 1) void k_gemm1tc(
    const int* __restrict__ node_ids, const float* __restrict__ emb,
    const float* __restrict__ b1, const float* __restrict__ W2,
    const float* __restrict__ b2)
{
    extern __shared__ char smc[];
    const uint32_t sb = smem_u32(smc);
    const int t = threadIdx.x, lane = t & 31, wid = t >> 5;
    const int wm = wid >> 2, wn = wid & 3;       // 2 x 4 warps
    const int m0 = blockIdx.x * TM;
    int*   rows_s = (int*)(smc + OFF_ROWS);
    float* b1s    = (float*)(smc + OFF_B1);
    float* b2s    = (float*)(smc + OFF_B2);

    if (t < TM) rows_s[t] = node_ids[m0 + t];
    b1s[t] = b1[t];
    if (t < CLS) b2s[t] = b2[t];
    __syncthreads();

    float acc[5][8][4];
    #pragma unroll
    for (int mt = 0; mt < 5; mt++)
        #pragma unroll
        for (int nt = 0; nt < 8; nt++)
            #pragma unroll
            for (int q = 0; q < 4; q++) acc[mt][nt][q] = 0.f;

    // prologue: stage chunks 0 and 1
    issue_chunk(sb, emb, rows_s, 0, t); CP_COMMIT();
    issue_chunk(sb, emb, rows_s, 1, t); CP_COMMIT();
    CP_WAIT1();
    __syncthreads();
    convert_chunk(smc, 0, t);
    __syncthreads();

    for (int ch = 0; ch < NCH; ch++) {
        const int buf = ch & 1;
        const uint32_t aH = sb + OFF_AS + buf*10240;
        const uint32_t bH = sb + OFF_BB + buf*16384;
        // ---- compute chunk ch (single fp16 pass) ----
        #pragma unroll
        for (int ks = 0; ks < 2; ks++) {
            const int kb = ks*16;
            uint32_t af[5][4], bf[8][2];
            #pragma unroll
            for (int mt = 0; mt < 5; mt++)
                ldsm4(af[mt], a_addr64(aH, wm*80 + mt*16, kb, lane));
            #pragma unroll
            for (int p = 0; p < 4; p++) {
                uint32_t r[4];
                ldsm4(r, b_addr64(bH, wn*64 + p*16, kb, lane));
                bf[p*2][0]=r[0]; bf[p*2][1]=r[1];
                bf[p*2+1][0]=r[2]; bf[p*2+1][1]=r[3];
            }
            #pragma unroll
            for (int mt = 0; mt < 5; mt++)
                #pragma unroll
                for (int nt = 0; nt < 8; nt++)
                    mma16816(acc[mt][nt], af[mt], bf[nt]);
        }
        __syncthreads();                         // all reads of buf done
        if (ch + 2 < NCH) { issue_chunk(sb, emb, rows_s, ch + 2, t); CP_COMMIT(); }
        if (ch + 1 < NCH) {
            if (ch + 2 < NCH) CP_WAIT1(); else CP_WAIT0();
            __syncthreads();
            convert_chunk(smc, ch + 1, t);
            __syncthreads();
        }
    }
    __syncthreads();

    // ---- epilogue 1: acc -> XS with +b1, ReLU ----
    float* XS = (float*)(smc + OFF_XS);
    {
        const int lr4 = lane >> 2, lc2 = (lane & 3)*2;
        #pragma unroll
        for (int mt = 0; mt < 5; mt++) {
            #pragma unroll
            for (int nt = 0; nt < 8; nt++) {
                int r0 = wm*80 + mt*16 + lr4;
                int c0 = wn*64 + nt*8 + lc2;
                float ba = b1s[c0], bb = b1s[c0+1];
                XS[r0*XS_STRIDE + c0]       = fmaxf(acc[mt][nt][0] + ba, 0.f);
                XS[r0*XS_STRIDE + c0 + 1]   = fmaxf(acc[mt][nt][1] + bb, 0.f);
                XS[(r0+8)*XS_STRIDE + c0]   = fmaxf(acc[mt][nt][2] + ba, 0.f);
                XS[(r0+8)*XS_STRIDE + c0+1] = fmaxf(acc[mt][nt][3] + bb, 0.f);
            }
        }
    }
    float* W2S  = (float*)(smc + OFF_W2S);
    float* HRED = (float*)(smc + OFF_HRED);
    for (int i = t; i < HID*CLS; i += 256) W2S[i] = W2[i];
    __syncthreads();

    // ---- epilogue 2: h = relu(x) @ W2, (row, K-half) split over 320 workers
    for (int p = t; p < 2*TM; p += 256) {
        int half = p / TM, row = p - half*TM;
        float hacc[CLS];
        #pragma unroll
        for (int c = 0; c < CLS; c++) hacc[c] = 0.f;
        const float* xr = XS + row*XS_STRIDE + half*128;
        #pragma unroll 4
        for (int n = 0; n < 128; n++) {
            float xv = xr[n];
            const float4* w4 = reinterpret_cast<const float4*>(
                W2S + (half*128 + n)*CLS);
            #pragma unroll
            for (int q = 0; q < 5; q++) {
                float4 w = w4[q];
                hacc[q*4+0] = fmaf(xv, w.x, hacc[q*4+0]);
                hacc[q*4+1] = fmaf(xv, w.y, hacc[q*4+1]);
                hacc[q*4+2] = fmaf(xv, w.z, hacc[q*4+2]);
                hacc[q*4+3] = fmaf(xv, w.w, hacc[q*4+3]);
            }
        }
        #pragma unroll
        for (int c = 0; c < CLS; c++) HRED[p*CLS + c] = hacc[c];
    }
    __syncthreads();
    if (t < TM) {
        #pragma unroll
        for (int c = 0; c < CLS; c++)
            g_h[(m0 + t)*CLS + c] =
                HRED[t*CLS + c] + HRED[(TM + t)*CLS + c] + b2s[c];
    }
}

// ---------------- K2: zero a feature buffer ----------------
__global__ __launch_bounds__(256) void k_zero(int which)
{
    float* p = which ? g_hB : g_h;
    int i = blockIdx.x*256 + threadIdx.x;      // NNODES*CLS/4 = 224000
    reinterpret_cast<float4*>(p)[i] = make_float4(0.f, 0.f, 0.f, 0.f);
}

// ---------------- K3: fused GAT layer, transposed/padded layout ----------
// z buffers [CLS][ZS], outputs at column p+3, 3-col zero halo each side.
#define ZS 384
#define GAT_SMEM (27008*4)   // 108032 bytes
__global__ __launch_bounds__(256) void k_gat(
    const float* __restrict__ gat_W, const float* __restrict__ a_src,
    const float* __restrict__ a_dst, int layer)
{
    extern __shared__ float gs[];
    float* zA   = gs;            // 7680: z0 (persists all hops)
    float* zB   = gs + 7680;     // h on load, then hop-0 out
    float* zC   = gs + 15360;    // hop-1 out
    float* att0 = gs + 23040;    // [350][4] float4 plane (w0..w3)
    float* att1 = gs + 24448;    // [350][4] float4 plane (w4..w6, 0)
    float* esb  = gs + 25856;    // 352
    float* edb  = gs + 26208;    // 352
    float* Wb   = gs + 26560;    // 400
    float* asb  = gs + 26960;    // 20
    float* adb  = gs + 26980;    // 20
    const int t = threadIdx.x;
    const int hd = blockIdx.x & 7, doc = blockIdx.x >> 3;
    const float* src = (layer == 0) ? g_h : g_hB;
    float*       dst = (layer == 0) ? g_hB : g_h;

    // load h transposed into zB: gmem [p][c] -> smem [c][p+3]
    const float4* hg = reinterpret_cast<const float4*>(src + (size_t)doc*LSEQ*CLS);
    for (int i = t; i < LSEQ*CLS/4; i += 256) {
        float4 v = hg[i];
        int f = i*4;
        int p = f / CLS, c = f % CLS;      // c in {0,4,8,12,16}
        zB[(c+0)*ZS + p+3] = v.x;
        zB[(c+1)*ZS + p+3] = v.y;
        zB[(c+2)*ZS + p+3] = v.z;
        zB[(c+3)*ZS + p+3] = v.w;
    }
    const float* Wg = gat_W + ((size_t)layer*HEADS + hd)*CLS*CLS;
    for (int i = t; i < CLS*CLS; i += 256) Wb[i] = Wg[i];
    if (t < CLS) {
        asb[t] = a_src[(layer*HEADS + hd)*CLS + t];
        adb[t] = a_dst[(layer*HEADS + hd)*CLS + t];
    }
    // zero halos of all three z buffers (cols 0..2 and 353..355)
    for (int i = t; i < 3*CLS*6; i += 256) {
        int buf = i / (CLS*6);
        int r   = (i % (CLS*6)) / 6;
        int k   = i % 6;
        int pos = (k < 3) ? k : (350 + k);
        float* z = (buf == 0) ? zA : (buf == 1) ? zB : zC;
        z[r*ZS + pos] = 0.f;
    }
    __syncthreads();

    // projection: zA[c][p+3] = sum_c2 h[p][c2] * W[c2][c]; es/ed scores
    for (int p = t; p < LSEQ; p += 256) {
        float zr[CLS];
        #pragma unroll
        for (int c = 0; c < CLS; c++) zr[c] = 0.f;
        #pragma unroll
        for (int c2 = 0; c2 < CLS; c2++) {
            float hv = zB[c2*ZS + p + 3];
            #pragma unroll
            for (int c = 0; c < CLS; c++)
                zr[c] = fmaf(hv, Wb[c2*CLS + c], zr[c]);
        }
        float es = 0.f, ed = 0.f;
        #pragma unroll
        for (int c = 0; c < CLS; c++) {
            es = fmaf(zr[c], asb[c], es);
            ed = fmaf(zr[c], adb[c], ed);
        }
        esb[p] = es; edb[p] = ed;
        #pragma unroll
        for (int c = 0; c < CLS; c++) zA[c*ZS + p + 3] = zr[c];
    }
    __syncthreads();

    // banded softmax -> att planes (float4 rows)
    for (int p = t; p < LSEQ; p += 256) {
        float ed = edb[p];
        float e[WIN], m = -1e30f;
        #pragma unroll
        for (int w = 0; w < WIN; w++) {
            int j = p - NGW + w;
            bool valid = (j >= 0) & (j < LSEQ);
            int jj = valid ? j : p;
            float ev = esb[jj] + ed;
            ev = ev > 0.f ? ev : 0.2f*ev;
            e[w] = valid ? ev : -1e30f;
            m = fmaxf(m, e[w]);
        }
        float ex[WIN], s = 0.f;
        #pragma unroll
        for (int w = 0; w < WIN; w++) {
            ex[w] = (e[w] > -1e29f) ? expf(e[w] - m) : 0.f;
            s += ex[w];
        }
        float inv = 1.f / (s + 1e-9f);
        reinterpret_cast<float4*>(att0)[p] =
            make_float4(ex[0]*inv, ex[1]*inv, ex[2]*inv, ex[3]*inv);
        reinterpret_cast<float4*>(att1)[p] =
            make_float4(ex[4]*inv, ex[5]*inv, ex[6]*inv, 0.f);
    }
    __syncthreads();

    // hops: zA -> zB -> zC -> gmem atomics (z0 term from zA, never clobbered)
    float* dsb = dst + (size_t)doc*LSEQ*CLS;
    #pragma unroll
    for (int hop = 0; hop < KHOPS; hop++) {
        const float* zin  = (hop == 0) ? zA : ((hop == 1) ? zB : zC);
        float*       zout = (hop == 0) ? zB : zC;
        for (int j = t; j < LSEQ*CLS; j += 256) {
            int c = j / LSEQ;
            int p = j - c*LSEQ;
            const float* zi = zin + c*ZS + p;
            float4 a0 = reinterpret_cast<const float4*>(att0)[p];
            float4 a1 = reinterpret_cast<const float4*>(att1)[p];
            float acc;
            acc = a0.x * zi[0];
            acc = fmaf(a0.y, zi[1], acc);
            acc = fmaf(a0.z, zi[2], acc);
            acc = fmaf(a0.w, zi[3], acc);
            acc = fmaf(a1.x, zi[4], acc);
            acc = fmaf(a1.y, zi[5], acc);
            acc = fmaf(a1.z, zi[6], acc);
            float v = fmaf(1.f - ALPHA, acc, ALPHA * zA[c*ZS + p + 3]);
            if (hop == KHOPS-1) {
                float e = (v > 0.f) ? v : expm1f(v);
                atomicAdd(&dsb[p*CLS + c], e * (1.f/HEADS));
            } else {
                zout[c*ZS + p + 3] = v;
            }
        }
        if (hop < KHOPS-1) __syncthreads();
    }
}

// ---------------- K4: gated readout ----------------
__global__ __launch_bounds__(256) void k_readout(
    const float* __restrict__ w_gate, const float* __restrict__ b_gate,
    float* __restrict__ out)
{
    __shared__ float wg[CLS];
    __shared__ float sred[240];
    const int t = threadIdx.x;
    if (t < CLS) wg[t] = w_gate[t];
    __syncthreads();
    const int doc = blockIdx.x;
    const float bg = b_gate[0];
    float acc = 0.f;
    if (t < 240) {
        int c = t % CLS, r = t / CLS;
        for (int p = r; p < LSEQ; p += 12) {
            const float* hr = g_h + (doc*LSEQ + p)*CLS;
            float dot = bg;
            #pragma unroll
            for (int k = 0; k < CLS; k++) dot = fmaf(hr[k], wg[k], dot);
            float gate = 1.f / (1.f + expf(-dot));
            acc = fmaf(gate, hr[c], acc);
        }
        sred[t] = acc;
    }
    __syncthreads();
    if (t < CLS) {
        float s = 0.f;
        #pragma unroll
        for (int r = 0; r < 12; r++) s += sred[r*CLS + t];
        out[doc*CLS + t] = s;
    }
}

// ---------------- launch ----------------
extern "C" void kernel_launch(void* const* d_in, const int* in_sizes, int n_in,
                              void* d_out, int out_size)
{
    const int*   node_ids = (const int*)  d_in[0];
    const float* emb    = (const float*) d_in[4];
    const float* W1     = (const float*) d_in[5];
    const float* b1     = (const float*) d_in[6];
    const float* W2     = (const float*) d_in[7];
    const float* b2     = (const float*) d_in[8];
    const float* gat_W  = (const float*) d_in[9];
    const float* a_src  = (const float*) d_in[10];
    const float* a_dst  = (const float*) d_in[11];
    const float* w_gate = (const float*) d_in[12];
    const float* b_gate = (const float*) d_in[13];
    float* out = (float*)d_out;

    cudaFuncSetAttribute(k_gemm1tc,
        cudaFuncAttributeMaxDynamicSharedMemorySize, GEMM_SMEM);
    cudaFuncSetAttribute(k_gat,
        cudaFuncAttributeMaxDynamicSharedMemorySize, GAT_SMEM);

    k_prepw<<<dim3(DIM/32, HID/32), dim3(32, 8)>>>(W1);                  // 192
    k_gemm1tc<<<NNODES/TM, 256, GEMM_SMEM>>>(node_ids, emb, b1, W2, b2); // 280
    for (int l = 0; l < LAYERS; l++) {
        k_zero<<<NNODES*CLS/1024, 256>>>(l == 0 ? 1 : 0);                // 875
        k_gat<<<B_DOCS*HEADS, 256, GAT_SMEM>>>(gat_W, a_src, a_dst, l);  // 1024
    }
    k_readout<<<B_DOCS, 256>>>(w_gate, b_gate, out);
}

// round 7
// speedup vs baseline: 3.6444x; 1.1308x over previous
#include <cuda_runtime.h>
#include <cuda_fp16.h>
#include <math.h>
#include <stdint.h>

// ---------------- problem constants ----------------
#define VOCAB   50000
#define B_DOCS  128
#define LSEQ    350
#define NGW     3
#define DIM     768
#define HID     256
#define CLS     20
#define HEADS   8
#define LAYERS  2
#define KHOPS   3
#define ALPHA   0.15f
#define NNODES  (B_DOCS*LSEQ)      // 44800
#define WIN     7

// ---------------- scratch ----------------
__device__ float g_h [NNODES*CLS];     // node features (ping)
__device__ float g_hB[NNODES*CLS];     // node features (pong)
__device__ __half g_Wh[HID*DIM];       // W1^T fp16  [256,768]

// ---------------- helpers ----------------
__device__ __forceinline__ uint32_t smem_u32(const void* p) {
    uint32_t a;
    asm("{ .reg .u64 t; cvta.to.shared.u64 t, %1; cvt.u32.u64 %0, t; }"
        : "=r"(a) : "l"(p));
    return a;
}
#define SWZ64(o) ((o) ^ (((o) >> 3) & 0x30))

__device__ __forceinline__ void ldsm4(uint32_t* r, uint32_t addr) {
    asm volatile("ldmatrix.sync.aligned.m8n8.x4.shared.b16 {%0,%1,%2,%3}, [%4];"
        : "=r"(r[0]), "=r"(r[1]), "=r"(r[2]), "=r"(r[3]) : "r"(addr));
}
__device__ __forceinline__ void mma16816(float* c, const uint32_t* a, const uint32_t* b) {
    asm volatile("mma.sync.aligned.m16n8k16.row.col.f32.f16.f16.f32 "
        "{%0,%1,%2,%3}, {%4,%5,%6,%7}, {%8,%9}, {%0,%1,%2,%3};"
        : "+f"(c[0]), "+f"(c[1]), "+f"(c[2]), "+f"(c[3])
        : "r"(a[0]), "r"(a[1]), "r"(a[2]), "r"(a[3]), "r"(b[0]), "r"(b[1]));
}
__device__ __forceinline__ void cpasync16(uint32_t dst, const void* src) {
    size_t gs = __cvta_generic_to_global(src);
    asm volatile("cp.async.cg.shared.global [%0], [%1], 16;"
                 :: "r"(dst), "l"(gs) : "memory");
}
#define CP_COMMIT() asm volatile("cp.async.commit_group;" ::: "memory")
#define CP_WAIT0()  asm volatile("cp.async.wait_group 0;" ::: "memory")
#define CP_WAIT1()  asm volatile("cp.async.wait_group 1;" ::: "memory")

// ---------------- K0: coalesced transpose of W1 -> fp16 ----------------
__global__ __launch_bounds__(256) void k_prepw(const float* __restrict__ W1)
{
    __shared__ float tile[32][33];
    const int k0 = blockIdx.x * 32;    // over DIM (24)
    const int n0 = blockIdx.y * 32;    // over HID (8)
    const int tx = threadIdx.x, ty = threadIdx.y;  // 32 x 8
    #pragma unroll
    for (int i = 0; i < 4; i++)
        tile[ty + i*8][tx] = W1[(k0 + ty + i*8)*HID + n0 + tx];
    __syncthreads();
    #pragma unroll
    for (int i = 0; i < 4; i++) {
        int n = n0 + ty + i*8;
        g_Wh[(size_t)n*DIM + k0 + tx] = __float2half_rn(tile[tx][ty + i*8]);
    }
}

// ---------------- K1: gather + GEMM1(fp16 1-pass mma) + GEMM2 fused ------
#define TM       160
#define KB       32
#define NCH      (DIM/KB)        // 24
#define OFF_ROWS 0               // 160 * 4
#define OFF_B1   768             // 256 * 4
#define OFF_B2   1792            // 20 * 4 (+pad)
#define OFF_AS   2048            // A fp16: 2 x 10240
#define OFF_AR   22528           // Araw fp32: 2 x 20480
#define OFF_BB   63488           // B fp16: 2 x 16384
#define XS_STRIDE 259
#define OFF_XS   2048            // 160*259*4 = 165760 -> 167808
#define OFF_W2S  167808          // 20480 -> 188288
#define OFF_HRED 188288          // 320*20*4 = 25600 -> 213888
#define GEMM_SMEM 213888

__device__ __forceinline__ uint32_t a_addr64(uint32_t base, int row0, int kb, int lane) {
    int q = lane >> 3, lr = lane & 7;
    int row = row0 + ((q & 1) << 3) + lr;
    int k   = kb + ((q >> 1) << 3);
    return base + SWZ64((uint32_t)(row*64 + k*2));
}
__device__ __forceinline__ uint32_t b_addr64(uint32_t base, int n0, int kb, int lane) {
    int q = lane >> 3, lr = lane & 7;
    int n = n0 + ((q >> 1) << 3) + lr;
    int k = kb + ((q & 1) << 3);
    return base + SWZ64((uint32_t)(n*64 + k*2));
}

__device__ __forceinline__ void issue_chunk(
    uint32_t sb, const float* __restrict__ emb, const int* rows_s, int ch, int t)
{
    const int buf = ch & 1;
    const int k0 = ch * KB;
    const uint32_t bdst = sb + OFF_BB + buf*16384;
    #pragma unroll
    for (int i = 0; i < 4; i++) {
        int idx = t + i*256;               // 1024 = 256n x 4c
        int n = idx >> 2, c = idx & 3;
        cpasync16(bdst + SWZ64((uint32_t)(n*64 + c*16)),
                  g_Wh + (size_t)n*DIM + k0 + c*8);
    }
    const uint32_t adst = sb + OFF_AR + buf*20480;
    #pragma unroll
    for (int i = 0; i < 5; i++) {
        int idx = t + i*256;               // 1280 = 160m x 8c
        int m = idx >> 3, c = idx & 7;
        cpasync16(adst + (uint32_t)(m*128 + c*16),
                  emb + (size_t)rows_s[m]*DIM + k0 + c*4);
    }
}

__device__ __forceinline__ void convert_chunk(char* smc, int ch, int t)
{
    const int buf = ch & 1;
    const char* raw = smc + OFF_AR + buf*20480;
    char* dH = smc + OFF_AS + buf*10240;
    #pragma unroll
    for (int i = 0; i < 5; i++) {
        int idx = t + i*256;
        int m = idx >> 3, g = idx & 7;
        float4 v = *reinterpret_cast<const float4*>(raw + m*128 + g*16);
        __half2 h0 = __float22half2_rn(make_float2(v.x, v.y));
        __half2 h1 = __float22half2_rn(make_float2(v.z, v.w));
        uint2 hv;
        hv.x = *reinterpret_cast<uint32_t*>(&h0);
        hv.y = *reinterpret_cast<uint32_t*>(&h1);
        *reinterpret_cast<uint2*>(dH + SWZ64((uint32_t)(m*64 + g*8))) = hv;
    }
}

__global__ __launch_bounds__(256, 1) void k_gemm1tc(
    const int* __restrict__ node_ids, const float* __restrict__ emb,
    const float* __restrict__ b1, const float* __restrict__ W2,
    const float* __restrict__ b2)
{
    extern __shared__ char smc[];
    const uint32_t sb = smem_u32(smc);
    const int t = threadIdx.x, lane = t & 31, wid = t >> 5;
    const int wm = wid >> 2, wn = wid & 3;       // 2 x 4 warps
    const int m0 = blockIdx.x * TM;
    int*   rows_s = (int*)(smc + OFF_ROWS);
    float* b1s    = (float*)(smc + OFF_B1);
    float* b2s    = (float*)(smc + OFF_B2);

    if (t < TM) rows_s[t] = node_ids[m0 + t];
    b1s[t] = b1[t];
    if (t < CLS) b2s[t] = b2[t];
    __syncthreads();

    float acc[5][8][4];
    #pragma unroll
    for (int mt = 0; mt < 5; mt++)
        #pragma unroll
        for (int nt = 0; nt < 8; nt++)
            #pragma unroll
            for (int q = 0; q < 4; q++) acc[mt][nt][q] = 0.f;

    // prologue: stage chunks 0 and 1
    issue_chunk(sb, emb, rows_s, 0, t); CP_COMMIT();
    issue_chunk(sb, emb, rows_s, 1, t); CP_COMMIT();
    CP_WAIT1();
    __syncthreads();
    convert_chunk(smc, 0, t);
    __syncthreads();

    for (int ch = 0; ch < NCH; ch++) {
        const int buf = ch & 1;
        const uint32_t aH = sb + OFF_AS + buf*10240;
        const uint32_t bH = sb + OFF_BB + buf*16384;
        // ---- compute chunk ch (single fp16 pass) ----
        #pragma unroll
        for (int ks = 0; ks < 2; ks++) {
            const int kb = ks*16;
            uint32_t af[5][4], bf[8][2];
            #pragma unroll
            for (int mt = 0; mt < 5; mt++)
                ldsm4(af[mt], a_addr64(aH, wm*80 + mt*16, kb, lane));
            #pragma unroll
            for (int p = 0; p < 4; p++) {
                uint32_t r[4];
                ldsm4(r, b_addr64(bH, wn*64 + p*16, kb, lane));
                bf[p*2][0]=r[0]; bf[p*2][1]=r[1];
                bf[p*2+1][0]=r[2]; bf[p*2+1][1]=r[3];
            }
            #pragma unroll
            for (int mt = 0; mt < 5; mt++)
                #pragma unroll
                for (int nt = 0; nt < 8; nt++)
                    mma16816(acc[mt][nt], af[mt], bf[nt]);
        }
        __syncthreads();                         // all reads of buf done
        if (ch + 2 < NCH) { issue_chunk(sb, emb, rows_s, ch + 2, t); CP_COMMIT(); }
        if (ch + 1 < NCH) {
            if (ch + 2 < NCH) CP_WAIT1(); else CP_WAIT0();
            __syncthreads();
            convert_chunk(smc, ch + 1, t);
            __syncthreads();
        }
    }
    __syncthreads();

    // ---- epilogue 1: acc -> XS with +b1, ReLU ----
    float* XS = (float*)(smc + OFF_XS);
    {
        const int lr4 = lane >> 2, lc2 = (lane & 3)*2;
        #pragma unroll
        for (int mt = 0; mt < 5; mt++) {
            #pragma unroll
            for (int nt = 0; nt < 8; nt++) {
                int r0 = wm*80 + mt*16 + lr4;
                int c0 = wn*64 + nt*8 + lc2;
                float ba = b1s[c0], bb = b1s[c0+1];
                XS[r0*XS_STRIDE + c0]       = fmaxf(acc[mt][nt][0] + ba, 0.f);
                XS[r0*XS_STRIDE + c0 + 1]   = fmaxf(acc[mt][nt][1] + bb, 0.f);
                XS[(r0+8)*XS_STRIDE + c0]   = fmaxf(acc[mt][nt][2] + ba, 0.f);
                XS[(r0+8)*XS_STRIDE + c0+1] = fmaxf(acc[mt][nt][3] + bb, 0.f);
            }
        }
    }
    float* W2S  = (float*)(smc + OFF_W2S);
    float* HRED = (float*)(smc + OFF_HRED);
    for (int i = t; i < HID*CLS; i += 256) W2S[i] = W2[i];
    __syncthreads();

    // ---- epilogue 2: h = relu(x) @ W2, (row, K-half) split over 320 workers
    for (int p = t; p < 2*TM; p += 256) {
        int half = p / TM, row = p - half*TM;
        float hacc[CLS];
        #pragma unroll
        for (int c = 0; c < CLS; c++) hacc[c] = 0.f;
        const float* xr = XS + row*XS_STRIDE + half*128;
        #pragma unroll 4
        for (int n = 0; n < 128; n++) {
            float xv = xr[n];
            const float4* w4 = reinterpret_cast<const float4*>(
                W2S + (half*128 + n)*CLS);
            #pragma unroll
            for (int q = 0; q < 5; q++) {
                float4 w = w4[q];
                hacc[q*4+0] = fmaf(xv, w.x, hacc[q*4+0]);
                hacc[q*4+1] = fmaf(xv, w.y, hacc[q*4+1]);
                hacc[q*4+2] = fmaf(xv, w.z, hacc[q*4+2]);
                hacc[q*4+3] = fmaf(xv, w.w, hacc[q*4+3]);
            }
        }
        #pragma unroll
        for (int c = 0; c < CLS; c++) HRED[p*CLS + c] = hacc[c];
    }
    __syncthreads();
    if (t < TM) {
        #pragma unroll
        for (int c = 0; c < CLS; c++)
            g_h[(m0 + t)*CLS + c] =
                HRED[t*CLS + c] + HRED[(TM + t)*CLS + c] + b2s[c];
    }
}

// ---------------- K2: zero a feature buffer ----------------
__global__ __launch_bounds__(256) void k_zero(int which)
{
    float* p = which ? g_hB : g_h;
    int i = blockIdx.x*256 + threadIdx.x;      // NNODES*CLS/4 = 224000
    reinterpret_cast<float4*>(p)[i] = make_float4(0.f, 0.f, 0.f, 0.f);
}

// ---------------- K3: fused GAT layer, [p][c] layout + row halos ---------
// z buffers: 356 rows x 20 cls (rows -3..352), logical p at row p+3.
// All stencil taps, z0 term, att and outputs are float4 (LDS/STS.128).
#define ZROWS 356
#define ZFL   (ZROWS*CLS)        // 7120 floats per buffer
#define OFF_zA 0
#define OFF_zB ZFL               // 7120
#define OFF_zC (2*ZFL)           // 14240
#define OFF_A0 (3*ZFL)           // 21360  (350 float4)
#define OFF_A1 (OFF_A0 + 1400)   // 22760
#define OFF_ES (OFF_A1 + 1400)   // 24160
#define OFF_ED (OFF_ES + 352)    // 24512
#define OFF_WB (OFF_ED + 352)    // 24864
#define OFF_AS2 (OFF_WB + 400)   // 25264
#define OFF_AD2 (OFF_AS2 + 20)   // 25284
#define GAT_FLOATS (OFF_AD2 + 28) // 25312
#define GAT_SMEM (GAT_FLOATS*4)   // 101248 bytes
__global__ __launch_bounds__(256) void k_gat(
    const float* __restrict__ gat_W, const float* __restrict__ a_src,
    const float* __restrict__ a_dst, int layer)
{
    extern __shared__ float gs[];
    float* zA   = gs + OFF_zA;   // z0, persists all hops
    float* zB   = gs + OFF_zB;   // h on load, then hop-0 out
    float* zC   = gs + OFF_zC;   // hop-1 out
    float* att0 = gs + OFF_A0;
    float* att1 = gs + OFF_A1;
    float* esb  = gs + OFF_ES;
    float* edb  = gs + OFF_ED;
    float* Wb   = gs + OFF_WB;
    float* asb  = gs + OFF_AS2;
    float* adb  = gs + OFF_AD2;
    const int t = threadIdx.x;
    const int hd = blockIdx.x & 7, doc = blockIdx.x >> 3;
    const float* src = (layer == 0) ? g_h : g_hB;
    float*       dst = (layer == 0) ? g_hB : g_h;

    // load h straight into zB rows 3..352 (float4 copy, no transpose)
    const float4* hg = reinterpret_cast<const float4*>(src + (size_t)doc*LSEQ*CLS);
    float4* zB4 = reinterpret_cast<float4*>(zB);
    for (int i = t; i < LSEQ*CLS/4; i += 256) zB4[i + 15] = hg[i];
    const float* Wg = gat_W + ((size_t)layer*HEADS + hd)*CLS*CLS;
    for (int i = t; i < CLS*CLS; i += 256) Wb[i] = Wg[i];
    if (t < CLS) {
        asb[t] = a_src[(layer*HEADS + hd)*CLS + t];
        adb[t] = a_dst[(layer*HEADS + hd)*CLS + t];
    }
    // zero halos (rows -3..-1 and 350..352) of all three buffers: 15 f4 each end
    if (t < 90) {
        int buf = t / 30, r = t % 30;
        float4* z = reinterpret_cast<float4*>(gs + buf*ZFL);
        int idx = (r < 15) ? r : (ZFL/4 - 30 + r);
        z[idx] = make_float4(0.f, 0.f, 0.f, 0.f);
    }
    __syncthreads();

    // projection: zA[p+3][c] = sum_c2 h[p][c2] * W[c2][c]; es/ed scores
    for (int p = t; p < LSEQ; p += 256) {
        const float4* hr4 = reinterpret_cast<const float4*>(zB + (p+3)*CLS);
        float hv[CLS];
        #pragma unroll
        for (int q = 0; q < 5; q++) {
            float4 v = hr4[q];
            hv[q*4+0] = v.x; hv[q*4+1] = v.y; hv[q*4+2] = v.z; hv[q*4+3] = v.w;
        }
        float zr[CLS];
        #pragma unroll
        for (int c = 0; c < CLS; c++) zr[c] = 0.f;
        #pragma unroll
        for (int c2 = 0; c2 < CLS; c2++) {
            #pragma unroll
            for (int c = 0; c < CLS; c++)
                zr[c] = fmaf(hv[c2], Wb[c2*CLS + c], zr[c]);
        }
        float es = 0.f, ed = 0.f;
        #pragma unroll
        for (int c = 0; c < CLS; c++) {
            es = fmaf(zr[c], asb[c], es);
            ed = fmaf(zr[c], adb[c], ed);
        }
        esb[p] = es; edb[p] = ed;
        float4* za4 = reinterpret_cast<float4*>(zA + (p+3)*CLS);
        #pragma unroll
        for (int q = 0; q < 5; q++)
            za4[q] = make_float4(zr[q*4+0], zr[q*4+1], zr[q*4+2], zr[q*4+3]);
    }
    __syncthreads();

    // banded softmax -> att planes (float4 rows)
    for (int p = t; p < LSEQ; p += 256) {
        float ed = edb[p];
        float e[WIN], m = -1e30f;
        #pragma unroll
        for (int w = 0; w < WIN; w++) {
            int j = p - NGW + w;
            bool valid = (j >= 0) & (j < LSEQ);
            int jj = valid ? j : p;
            float ev = esb[jj] + ed;
            ev = ev > 0.f ? ev : 0.2f*ev;
            e[w] = valid ? ev : -1e30f;
            m = fmaxf(m, e[w]);
        }
        float ex[WIN], s = 0.f;
        #pragma unroll
        for (int w = 0; w < WIN; w++) {
            ex[w] = (e[w] > -1e29f) ? expf(e[w] - m) : 0.f;
            s += ex[w];
        }
        float inv = 1.f / (s + 1e-9f);
        reinterpret_cast<float4*>(att0)[p] =
            make_float4(ex[0]*inv, ex[1]*inv, ex[2]*inv, ex[3]*inv);
        reinterpret_cast<float4*>(att1)[p] =
            make_float4(ex[4]*inv, ex[5]*inv, ex[6]*inv, 0.f);
    }
    __syncthreads();

    // hops: zA -> zB -> zC -> gmem atomics; all accesses float4
    float* dsb = dst + (size_t)doc*LSEQ*CLS;
    #pragma unroll
    for (int hop = 0; hop < KHOPS; hop++) {
        const float4* zin4  = reinterpret_cast<const float4*>(
            (hop == 0) ? zA : ((hop == 1) ? zB : zC));
        float4* zout4 = reinterpret_cast<float4*>((hop == 0) ? zB : zC);
        for (int j = t; j < LSEQ*CLS/4; j += 256) {
            int p = j / 5;
            int g = j - p*5;              // float4 group within row
            float4 a0 = reinterpret_cast<const float4*>(att0)[p];
            float4 a1 = reinterpret_cast<const float4*>(att1)[p];
            // taps at buffer rows p..p+6 (logical p-3..p+3)
            const float4* zi = zin4 + p*5 + g;
            float4 s0 = zi[0];
            float4 s1 = zi[5];
            float4 s2 = zi[10];
            float4 s3 = zi[15];
            float4 s4 = zi[20];
            float4 s5 = zi[25];
            float4 s6 = zi[30];
            float4 acc;
            acc.x = a0.x*s0.x; acc.y = a0.x*s0.y; acc.z = a0.x*s0.z; acc.w = a0.x*s0.w;
            acc.x = fmaf(a0.y, s1.x, acc.x); acc.y = fmaf(a0.y, s1.y, acc.y);
            acc.z = fmaf(a0.y, s1.z, acc.z); acc.w = fmaf(a0.y, s1.w, acc.w);
            acc.x = fmaf(a0.z, s2.x, acc.x); acc.y = fmaf(a0.z, s2.y, acc.y);
            acc.z = fmaf(a0.z, s2.z, acc.z); acc.w = fmaf(a0.z, s2.w, acc.w);
            acc.x = fmaf(a0.w, s3.x, acc.x); acc.y = fmaf(a0.w, s3.y, acc.y);
            acc.z = fmaf(a0.w, s3.z, acc.z); acc.w = fmaf(a0.w, s3.w, acc.w);
            acc.x = fmaf(a1.x, s4.x, acc.x); acc.y = fmaf(a1.x, s4.y, acc.y);
            acc.z = fmaf(a1.x, s4.z, acc.z); acc.w = fmaf(a1.x, s4.w, acc.w);
            acc.x = fmaf(a1.y, s5.x, acc.x); acc.y = fmaf(a1.y, s5.y, acc.y);
            acc.z = fmaf(a1.y, s5.z, acc.z); acc.w = fmaf(a1.y, s5.w, acc.w);
            acc.x = fmaf(a1.z, s6.x, acc.x); acc.y = fmaf(a1.z, s6.y, acc.y);
            acc.z = fmaf(a1.z, s6.z, acc.z); acc.w = fmaf(a1.z, s6.w, acc.w);
            float4 z0v = reinterpret_cast<const float4*>(zA)[(p+3)*5 + g];
            float4 v;
            v.x = fmaf(1.f - ALPHA, acc.x, ALPHA*z0v.x);
            v.y = fmaf(1.f - ALPHA, acc.y, ALPHA*z0v.y);
            v.z = fmaf(1.f - ALPHA, acc.z, ALPHA*z0v.z);
            v.w = fmaf(1.f - ALPHA, acc.w, ALPHA*z0v.w);
            if (hop == KHOPS-1) {
                float* o = dsb + p*CLS + g*4;
                float ex0 = (v.x > 0.f) ? v.x : expm1f(v.x);
                float ex1 = (v.y > 0.f) ? v.y : expm1f(v.y);
                float ex2 = (v.z > 0.f) ? v.z : expm1f(v.z);
                float ex3 = (v.w > 0.f) ? v.w : expm1f(v.w);
                atomicAdd(o+0, ex0 * (1.f/HEADS));
                atomicAdd(o+1, ex1 * (1.f/HEADS));
                atomicAdd(o+2, ex2 * (1.f/HEADS));
                atomicAdd(o+3, ex3 * (1.f/HEADS));
            } else {
                zout4[(p+3)*5 + g] = v;
            }
        }
        if (hop < KHOPS-1) __syncthreads();
    }
}

// ---------------- K4: gated readout ----------------
__global__ __launch_bounds__(256) void k_readout(
    const float* __restrict__ w_gate, const float* __restrict__ b_gate,
    float* __restrict__ out)
{
    __shared__ float wg[CLS];
    __shared__ float sred[240];
    const int t = threadIdx.x;
    if (t < CLS) wg[t] = w_gate[t];
    __syncthreads();
    const int doc = blockIdx.x;
    const float bg = b_gate[0];
    float acc = 0.f;
    if (t < 240) {
        int c = t % CLS, r = t / CLS;
        for (int p = r; p < LSEQ; p += 12) {
            const float* hr = g_h + (doc*LSEQ + p)*CLS;
            float dot = bg;
            #pragma unroll
            for (int k = 0; k < CLS; k++) dot = fmaf(hr[k], wg[k], dot);
            float gate = 1.f / (1.f + expf(-dot));
            acc = fmaf(gate, hr[c], acc);
        }
        sred[t] = acc;
    }
    __syncthreads();
    if (t < CLS) {
        float s = 0.f;
        #pragma unroll
        for (int r = 0; r < 12; r++) s += sred[r*CLS + t];
        out[doc*CLS + t] = s;
    }
}

// ---------------- launch ----------------
extern "C" void kernel_launch(void* const* d_in, const int* in_sizes, int n_in,
                              void* d_out, int out_size)
{
    const int*   node_ids = (const int*)  d_in[0];
    const float* emb    = (const float*) d_in[4];
    const float* W1     = (const float*) d_in[5];
    const float* b1     = (const float*) d_in[6];
    const float* W2     = (const float*) d_in[7];
    const float* b2     = (const float*) d_in[8];
    const float* gat_W  = (const float*) d_in[9];
    const float* a_src  = (const float*) d_in[10];
    const float* a_dst  = (const float*) d_in[11];
    const float* w_gate = (const float*) d_in[12];
    const float* b_gate = (const float*) d_in[13];
    float* out = (float*)d_out;

    cudaFuncSetAttribute(k_gemm1tc,
        cudaFuncAttributeMaxDynamicSharedMemorySize, GEMM_SMEM);
    cudaFuncSetAttribute(k_gat,
        cudaFuncAttributeMaxDynamicSharedMemorySize, GAT_SMEM);

    k_prepw<<<dim3(DIM/32, HID/32), dim3(32, 8)>>>(W1);                  // 192
    k_gemm1tc<<<NNODES/TM, 256, GEMM_SMEM>>>(node_ids, emb, b1, W2, b2); // 280
    for (int l = 0; l < LAYERS; l++) {
        k_zero<<<NNODES*CLS/1024, 256>>>(l == 0 ? 1 : 0);                // 875
        k_gat<<<B_DOCS*HEADS, 256, GAT_SMEM>>>(gat_W, a_src, a_dst, l);  // 1024
    }
    k_readout<<<B_DOCS, 256>>>(w_gate, b_gate, out);
}

// round 8
// speedup vs baseline: 4.1708x; 1.1445x over previous
#include <cuda_runtime.h>
#include <cuda_fp16.h>
#include <math.h>
#include <stdint.h>

// ---------------- problem constants ----------------
#define VOCAB   50000
#define B_DOCS  128
#define LSEQ    350
#define NGW     3
#define DIM     768
#define HID     256
#define CLS     20
#define HEADS   8
#define LAYERS  2
#define KHOPS   3
#define ALPHA   0.15f
#define NNODES  (B_DOCS*LSEQ)      // 44800
#define WIN     7

// ---------------- scratch ----------------
__device__ float g_h [NNODES*CLS];     // node features (ping)
__device__ float g_hB[NNODES*CLS];     // node features (pong)
__device__ __half g_Wh[HID*DIM];       // W1^T fp16  [256,768]

// ---------------- helpers ----------------
__device__ __forceinline__ uint32_t smem_u32(const void* p) {
    uint32_t a;
    asm("{ .reg .u64 t; cvta.to.shared.u64 t, %1; cvt.u32.u64 %0, t; }"
        : "=r"(a) : "l"(p));
    return a;
}
#define SWZ64(o) ((o) ^ (((o) >> 3) & 0x30))

__device__ __forceinline__ void ldsm4(uint32_t* r, uint32_t addr) {
    asm volatile("ldmatrix.sync.aligned.m8n8.x4.shared.b16 {%0,%1,%2,%3}, [%4];"
        : "=r"(r[0]), "=r"(r[1]), "=r"(r[2]), "=r"(r[3]) : "r"(addr));
}
__device__ __forceinline__ void mma16816(float* c, const uint32_t* a, const uint32_t* b) {
    asm volatile("mma.sync.aligned.m16n8k16.row.col.f32.f16.f16.f32 "
        "{%0,%1,%2,%3}, {%4,%5,%6,%7}, {%8,%9}, {%0,%1,%2,%3};"
        : "+f"(c[0]), "+f"(c[1]), "+f"(c[2]), "+f"(c[3])
        : "r"(a[0]), "r"(a[1]), "r"(a[2]), "r"(a[3]), "r"(b[0]), "r"(b[1]));
}
__device__ __forceinline__ void cpasync16(uint32_t dst, const void* src) {
    size_t gs = __cvta_generic_to_global(src);
    asm volatile("cp.async.cg.shared.global [%0], [%1], 16;"
                 :: "r"(dst), "l"(gs) : "memory");
}
#define CP_COMMIT() asm volatile("cp.async.commit_group;" ::: "memory")
#define CP_WAIT0()  asm volatile("cp.async.wait_group 0;" ::: "memory")
#define CP_WAIT1()  asm volatile("cp.async.wait_group 1;" ::: "memory")

// ---------------- K0: coalesced transpose of W1 -> fp16 ----------------
__global__ __launch_bounds__(256) void k_prepw(const float* __restrict__ W1)
{
    __shared__ float tile[32][33];
    const int k0 = blockIdx.x * 32;    // over DIM (24)
    const int n0 = blockIdx.y * 32;    // over HID (8)
    const int tx = threadIdx.x, ty = threadIdx.y;  // 32 x 8
    #pragma unroll
    for (int i = 0; i < 4; i++)
        tile[ty + i*8][tx] = W1[(k0 + ty + i*8)*HID + n0 + tx];
    __syncthreads();
    #pragma unroll
    for (int i = 0; i < 4; i++) {
        int n = n0 + ty + i*8;
        g_Wh[(size_t)n*DIM + k0 + tx] = __float2half_rn(tile[tx][ty + i*8]);
    }
}

// ---------------- K1: gather + GEMM1(fp16 1-pass mma) + GEMM2 fused ------
#define TM       160
#define KB       32
#define NCH      (DIM/KB)        // 24
#define OFF_ROWS 0               // 160 * 4
#define OFF_B1   768             // 256 * 4
#define OFF_B2   1792            // 20 * 4 (+pad)
#define OFF_AS   2048            // A fp16: 2 x 10240
#define OFF_AR   22528           // Araw fp32: 2 x 20480
#define OFF_BB   63488           // B fp16: 2 x 16384
#define XS_STRIDE 259
#define OFF_XS   2048            // 160*259*4 = 165760 -> 167808
#define OFF_W2S  167808          // 20480 -> 188288
#define OFF_HRED 188288          // 320*20*4 = 25600 -> 213888
#define GEMM_SMEM 213888

__device__ __forceinline__ uint32_t a_addr64(uint32_t base, int row0, int kb, int lane) {
    int q = lane >> 3, lr = lane & 7;
    int row = row0 + ((q & 1) << 3) + lr;
    int k   = kb + ((q >> 1) << 3);
    return base + SWZ64((uint32_t)(row*64 + k*2));
}
__device__ __forceinline__ uint32_t b_addr64(uint32_t base, int n0, int kb, int lane) {
    int q = lane >> 3, lr = lane & 7;
    int n = n0 + ((q >> 1) << 3) + lr;
    int k = kb + ((q & 1) << 3);
    return base + SWZ64((uint32_t)(n*64 + k*2));
}

__device__ __forceinline__ void issue_chunk(
    uint32_t sb, const float* __restrict__ emb, const int* rows_s, int ch, int t)
{
    const int buf = ch & 1;
    const int k0 = ch * KB;
    const uint32_t bdst = sb + OFF_BB + buf*16384;
    #pragma unroll
    for (int i = 0; i < 4; i++) {
        int idx = t + i*256;               // 1024 = 256n x 4c
        int n = idx >> 2, c = idx & 3;
        cpasync16(bdst + SWZ64((uint32_t)(n*64 + c*16)),
                  g_Wh + (size_t)n*DIM + k0 + c*8);
    }
    const uint32_t adst = sb + OFF_AR + buf*20480;
    #pragma unroll
    for (int i = 0; i < 5; i++) {
        int idx = t + i*256;               // 1280 = 160m x 8c
        int m = idx >> 3, c = idx & 7;
        cpasync16(adst + (uint32_t)(m*128 + c*16),
                  emb + (size_t)rows_s[m]*DIM + k0 + c*4);
    }
}

__device__ __forceinline__ void convert_chunk(char* smc, int ch, int t)
{
    const int buf = ch & 1;
    const char* raw = smc + OFF_AR + buf*20480;
    char* dH = smc + OFF_AS + buf*10240;
    #pragma unroll
    for (int i = 0; i < 5; i++) {
        int idx = t + i*256;
        int m = idx >> 3, g = idx & 7;
        float4 v = *reinterpret_cast<const float4*>(raw + m*128 + g*16);
        __half2 h0 = __float22half2_rn(make_float2(v.x, v.y));
        __half2 h1 = __float22half2_rn(make_float2(v.z, v.w));
        uint2 hv;
        hv.x = *reinterpret_cast<uint32_t*>(&h0);
        hv.y = *reinterpret_cast<uint32_t*>(&h1);
        *reinterpret_cast<uint2*>(dH + SWZ64((uint32_t)(m*64 + g*8))) = hv;
    }
}

__global__ __launch_bounds__(256, 1) void k_gemm1tc(
    const int* __restrict__ node_ids, const float* __restrict__ emb,
    const float* __restrict__ b1, const float* __restrict__ W2,
    const float* __restrict__ b2)
{
    extern __shared__ char smc[];
    const uint32_t sb = smem_u32(smc);
    const int t = threadIdx.x, lane = t & 31, wid = t >> 5;
    const int wm = wid >> 2, wn = wid & 3;       // 2 x 4 warps
    const int m0 = blockIdx.x * TM;
    int*   rows_s = (int*)(smc + OFF_ROWS);
    float* b1s    = (float*)(smc + OFF_B1);
    float* b2s    = (float*)(smc + OFF_B2);

    if (t < TM) rows_s[t] = node_ids[m0 + t];
    b1s[t] = b1[t];
    if (t < CLS) b2s[t] = b2[t];
    __syncthreads();

    // zero this block's slice of g_hB (layer-0 accumulation target)
    {
        float4* zb = reinterpret_cast<float4*>(g_hB + (size_t)m0*CLS);
        #pragma unroll
        for (int i = t; i < TM*CLS/4; i += 256)
            zb[i] = make_float4(0.f, 0.f, 0.f, 0.f);
    }

    float acc[5][8][4];
    #pragma unroll
    for (int mt = 0; mt < 5; mt++)
        #pragma unroll
        for (int nt = 0; nt < 8; nt++)
            #pragma unroll
            for (int q = 0; q < 4; q++) acc[mt][nt][q] = 0.f;

    // prologue: stage chunks 0 and 1
    issue_chunk(sb, emb, rows_s, 0, t); CP_COMMIT();
    issue_chunk(sb, emb, rows_s, 1, t); CP_COMMIT();
    CP_WAIT1();
    __syncthreads();
    convert_chunk(smc, 0, t);
    __syncthreads();

    for (int ch = 0; ch < NCH; ch++) {
        const int buf = ch & 1;
        const uint32_t aH = sb + OFF_AS + buf*10240;
        const uint32_t bH = sb + OFF_BB + buf*16384;
        // ---- compute chunk ch (single fp16 pass) ----
        #pragma unroll
        for (int ks = 0; ks < 2; ks++) {
            const int kb = ks*16;
            uint32_t af[5][4], bf[8][2];
            #pragma unroll
            for (int mt = 0; mt < 5; mt++)
                ldsm4(af[mt], a_addr64(aH, wm*80 + mt*16, kb, lane));
            #pragma unroll
            for (int p = 0; p < 4; p++) {
                uint32_t r[4];
                ldsm4(r, b_addr64(bH, wn*64 + p*16, kb, lane));
                bf[p*2][0]=r[0]; bf[p*2][1]=r[1];
                bf[p*2+1][0]=r[2]; bf[p*2+1][1]=r[3];
            }
            #pragma unroll
            for (int mt = 0; mt < 5; mt++)
                #pragma unroll
                for (int nt = 0; nt < 8; nt++)
                    mma16816(acc[mt][nt], af[mt], bf[nt]);
        }
        __syncthreads();                         // all reads of buf done
        if (ch + 2 < NCH) { issue_chunk(sb, emb, rows_s, ch + 2, t); CP_COMMIT(); }
        if (ch + 1 < NCH) {
            if (ch + 2 < NCH) CP_WAIT1(); else CP_WAIT0();
            __syncthreads();
            convert_chunk(smc, ch + 1, t);
            __syncthreads();
        }
    }
    __syncthreads();

    // ---- epilogue 1: acc -> XS with +b1, ReLU ----
    float* XS = (float*)(smc + OFF_XS);
    {
        const int lr4 = lane >> 2, lc2 = (lane & 3)*2;
        #pragma unroll
        for (int mt = 0; mt < 5; mt++) {
            #pragma unroll
            for (int nt = 0; nt < 8; nt++) {
                int r0 = wm*80 + mt*16 + lr4;
                int c0 = wn*64 + nt*8 + lc2;
                float ba = b1s[c0], bb = b1s[c0+1];
                XS[r0*XS_STRIDE + c0]       = fmaxf(acc[mt][nt][0] + ba, 0.f);
                XS[r0*XS_STRIDE + c0 + 1]   = fmaxf(acc[mt][nt][1] + bb, 0.f);
                XS[(r0+8)*XS_STRIDE + c0]   = fmaxf(acc[mt][nt][2] + ba, 0.f);
                XS[(r0+8)*XS_STRIDE + c0+1] = fmaxf(acc[mt][nt][3] + bb, 0.f);
            }
        }
    }
    float* W2S  = (float*)(smc + OFF_W2S);
    float* HRED = (float*)(smc + OFF_HRED);
    for (int i = t; i < HID*CLS; i += 256) W2S[i] = W2[i];
    __syncthreads();

    // ---- epilogue 2: h = relu(x) @ W2, (row, K-half) split over 320 workers
    for (int p = t; p < 2*TM; p += 256) {
        int half = p / TM, row = p - half*TM;
        float hacc[CLS];
        #pragma unroll
        for (int c = 0; c < CLS; c++) hacc[c] = 0.f;
        const float* xr = XS + row*XS_STRIDE + half*128;
        #pragma unroll 4
        for (int n = 0; n < 128; n++) {
            float xv = xr[n];
            const float4* w4 = reinterpret_cast<const float4*>(
                W2S + (half*128 + n)*CLS);
            #pragma unroll
            for (int q = 0; q < 5; q++) {
                float4 w = w4[q];
                hacc[q*4+0] = fmaf(xv, w.x, hacc[q*4+0]);
                hacc[q*4+1] = fmaf(xv, w.y, hacc[q*4+1]);
                hacc[q*4+2] = fmaf(xv, w.z, hacc[q*4+2]);
                hacc[q*4+3] = fmaf(xv, w.w, hacc[q*4+3]);
            }
        }
        #pragma unroll
        for (int c = 0; c < CLS; c++) HRED[p*CLS + c] = hacc[c];
    }
    __syncthreads();
    if (t < TM) {
        #pragma unroll
        for (int c = 0; c < CLS; c++)
            g_h[(m0 + t)*CLS + c] =
                HRED[t*CLS + c] + HRED[(TM + t)*CLS + c] + b2s[c];
    }
}

// ---------------- K2: zero a feature buffer ----------------
__global__ __launch_bounds__(256) void k_zero(int which)
{
    float* p = which ? g_hB : g_h;
    int i = blockIdx.x*256 + threadIdx.x;      // NNODES*CLS/4 = 224000
    reinterpret_cast<float4*>(p)[i] = make_float4(0.f, 0.f, 0.f, 0.f);
}

// ---------------- K3: fused GAT layer, [p][c] layout + row halos ---------
// z buffers: 356 rows x 20 cls (rows -3..352), logical p at row p+3.
// All stencil taps, z0 term, att and outputs are float4 (LDS/STS.128).
#define GT 512
#define ZROWS 356
#define ZFL   (ZROWS*CLS)        // 7120 floats per buffer
#define OFF_zA 0
#define OFF_zB ZFL               // 7120
#define OFF_zC (2*ZFL)           // 14240
#define OFF_A0 (3*ZFL)           // 21360  (350 float4)
#define OFF_A1 (OFF_A0 + 1400)   // 22760
#define OFF_ES (OFF_A1 + 1400)   // 24160
#define OFF_ED (OFF_ES + 352)    // 24512
#define OFF_WB (OFF_ED + 352)    // 24864
#define OFF_AS2 (OFF_WB + 400)   // 25264
#define OFF_AD2 (OFF_AS2 + 20)   // 25284
#define GAT_FLOATS (OFF_AD2 + 28) // 25312
#define GAT_SMEM (GAT_FLOATS*4)   // 101248 bytes
__global__ __launch_bounds__(GT, 2) void k_gat(
    const float* __restrict__ gat_W, const float* __restrict__ a_src,
    const float* __restrict__ a_dst, int layer)
{
    extern __shared__ float gs[];
    float* zA   = gs + OFF_zA;   // z0, persists all hops
    float* zB   = gs + OFF_zB;   // h on load, then hop-0 out
    float* zC   = gs + OFF_zC;   // hop-1 out
    float* att0 = gs + OFF_A0;
    float* att1 = gs + OFF_A1;
    float* esb  = gs + OFF_ES;
    float* edb  = gs + OFF_ED;
    float* Wb   = gs + OFF_WB;
    float* asb  = gs + OFF_AS2;
    float* adb  = gs + OFF_AD2;
    const int t = threadIdx.x;
    const int hd = blockIdx.x & 7, doc = blockIdx.x >> 3;
    const float* src = (layer == 0) ? g_h : g_hB;
    float*       dst = (layer == 0) ? g_hB : g_h;

    // load h straight into zB rows 3..352 (float4 copy, no transpose)
    const float4* hg = reinterpret_cast<const float4*>(src + (size_t)doc*LSEQ*CLS);
    float4* zB4 = reinterpret_cast<float4*>(zB);
    for (int i = t; i < LSEQ*CLS/4; i += GT) zB4[i + 15] = hg[i];
    const float* Wg = gat_W + ((size_t)layer*HEADS + hd)*CLS*CLS;
    for (int i = t; i < CLS*CLS; i += GT) Wb[i] = Wg[i];
    if (t >= GT-32 && t < GT-32+CLS) {
        int c = t - (GT-32);
        asb[c] = a_src[(layer*HEADS + hd)*CLS + c];
        adb[c] = a_dst[(layer*HEADS + hd)*CLS + c];
    }
    // zero halos (rows -3..-1 and 350..352) of all three buffers: 15 f4 each end
    if (t >= GT-128 && t < GT-128+90) {
        int r0 = t - (GT-128);
        int buf = r0 / 30, r = r0 % 30;
        float4* z = reinterpret_cast<float4*>(gs + buf*ZFL);
        int idx = (r < 15) ? r : (ZFL/4 - 30 + r);
        z[idx] = make_float4(0.f, 0.f, 0.f, 0.f);
    }
    __syncthreads();

    // projection: zA[p+3][c] = sum_c2 h[p][c2] * W[c2][c]; es/ed scores
    for (int p = t; p < LSEQ; p += GT) {
        const float4* hr4 = reinterpret_cast<const float4*>(zB + (p+3)*CLS);
        float hv[CLS];
        #pragma unroll
        for (int q = 0; q < 5; q++) {
            float4 v = hr4[q];
            hv[q*4+0] = v.x; hv[q*4+1] = v.y; hv[q*4+2] = v.z; hv[q*4+3] = v.w;
        }
        float zr[CLS];
        #pragma unroll
        for (int c = 0; c < CLS; c++) zr[c] = 0.f;
        #pragma unroll
        for (int c2 = 0; c2 < CLS; c2++) {
            #pragma unroll
            for (int c = 0; c < CLS; c++)
                zr[c] = fmaf(hv[c2], Wb[c2*CLS + c], zr[c]);
        }
        float es = 0.f, ed = 0.f;
        #pragma unroll
        for (int c = 0; c < CLS; c++) {
            es = fmaf(zr[c], asb[c], es);
            ed = fmaf(zr[c], adb[c], ed);
        }
        esb[p] = es; edb[p] = ed;
        float4* za4 = reinterpret_cast<float4*>(zA + (p+3)*CLS);
        #pragma unroll
        for (int q = 0; q < 5; q++)
            za4[q] = make_float4(zr[q*4+0], zr[q*4+1], zr[q*4+2], zr[q*4+3]);
    }
    __syncthreads();

    // banded softmax -> att planes (float4 rows)
    for (int p = t; p < LSEQ; p += GT) {
        float ed = edb[p];
        float e[WIN], m = -1e30f;
        #pragma unroll
        for (int w = 0; w < WIN; w++) {
            int j = p - NGW + w;
            bool valid = (j >= 0) & (j < LSEQ);
            int jj = valid ? j : p;
            float ev = esb[jj] + ed;
            ev = ev > 0.f ? ev : 0.2f*ev;
            e[w] = valid ? ev : -1e30f;
            m = fmaxf(m, e[w]);
        }
        float ex[WIN], s = 0.f;
        #pragma unroll
        for (int w = 0; w < WIN; w++) {
            ex[w] = (e[w] > -1e29f) ? expf(e[w] - m) : 0.f;
            s += ex[w];
        }
        float inv = 1.f / (s + 1e-9f);
        reinterpret_cast<float4*>(att0)[p] =
            make_float4(ex[0]*inv, ex[1]*inv, ex[2]*inv, ex[3]*inv);
        reinterpret_cast<float4*>(att1)[p] =
            make_float4(ex[4]*inv, ex[5]*inv, ex[6]*inv, 0.f);
    }
    __syncthreads();

    // hops: zA -> zB -> zC -> gmem atomics; all accesses float4
    float* dsb = dst + (size_t)doc*LSEQ*CLS;
    #pragma unroll
    for (int hop = 0; hop < KHOPS; hop++) {
        const float4* zin4  = reinterpret_cast<const float4*>(
            (hop == 0) ? zA : ((hop == 1) ? zB : zC));
        float4* zout4 = reinterpret_cast<float4*>((hop == 0) ? zB : zC);
        for (int j = t; j < LSEQ*CLS/4; j += GT) {
            int p = j / 5;
            int g = j - p*5;              // float4 group within row
            float4 a0 = reinterpret_cast<const float4*>(att0)[p];
            float4 a1 = reinterpret_cast<const float4*>(att1)[p];
            // taps at buffer rows p..p+6 (logical p-3..p+3)
            const float4* zi = zin4 + p*5 + g;
            float4 s0 = zi[0];
            float4 s1 = zi[5];
            float4 s2 = zi[10];
            float4 s3 = zi[15];
            float4 s4 = zi[20];
            float4 s5 = zi[25];
            float4 s6 = zi[30];
            float4 acc;
            acc.x = a0.x*s0.x; acc.y = a0.x*s0.y; acc.z = a0.x*s0.z; acc.w = a0.x*s0.w;
            acc.x = fmaf(a0.y, s1.x, acc.x); acc.y = fmaf(a0.y, s1.y, acc.y);
            acc.z = fmaf(a0.y, s1.z, acc.z); acc.w = fmaf(a0.y, s1.w, acc.w);
            acc.x = fmaf(a0.z, s2.x, acc.x); acc.y = fmaf(a0.z, s2.y, acc.y);
            acc.z = fmaf(a0.z, s2.z, acc.z); acc.w = fmaf(a0.z, s2.w, acc.w);
            acc.x = fmaf(a0.w, s3.x, acc.x); acc.y = fmaf(a0.w, s3.y, acc.y);
            acc.z = fmaf(a0.w, s3.z, acc.z); acc.w = fmaf(a0.w, s3.w, acc.w);
            acc.x = fmaf(a1.x, s4.x, acc.x); acc.y = fmaf(a1.x, s4.y, acc.y);
            acc.z = fmaf(a1.x, s4.z, acc.z); acc.w = fmaf(a1.x, s4.w, acc.w);
            acc.x = fmaf(a1.y, s5.x, acc.x); acc.y = fmaf(a1.y, s5.y, acc.y);
            acc.z = fmaf(a1.y, s5.z, acc.z); acc.w = fmaf(a1.y, s5.w, acc.w);
            acc.x = fmaf(a1.z, s6.x, acc.x); acc.y = fmaf(a1.z, s6.y, acc.y);
            acc.z = fmaf(a1.z, s6.z, acc.z); acc.w = fmaf(a1.z, s6.w, acc.w);
            float4 z0v = reinterpret_cast<const float4*>(zA)[(p+3)*5 + g];
            float4 v;
            v.x = fmaf(1.f - ALPHA, acc.x, ALPHA*z0v.x);
            v.y = fmaf(1.f - ALPHA, acc.y, ALPHA*z0v.y);
            v.z = fmaf(1.f - ALPHA, acc.z, ALPHA*z0v.z);
            v.w = fmaf(1.f - ALPHA, acc.w, ALPHA*z0v.w);
            if (hop == KHOPS-1) {
                float* o = dsb + p*CLS + g*4;
                float ex0 = (v.x > 0.f) ? v.x : expm1f(v.x);
                float ex1 = (v.y > 0.f) ? v.y : expm1f(v.y);
                float ex2 = (v.z > 0.f) ? v.z : expm1f(v.z);
                float ex3 = (v.w > 0.f) ? v.w : expm1f(v.w);
                atomicAdd(o+0, ex0 * (1.f/HEADS));
                atomicAdd(o+1, ex1 * (1.f/HEADS));
                atomicAdd(o+2, ex2 * (1.f/HEADS));
                atomicAdd(o+3, ex3 * (1.f/HEADS));
            } else {
                zout4[(p+3)*5 + g] = v;
            }
        }
        if (hop < KHOPS-1) __syncthreads();
    }
}

// ---------------- K4: gated readout ----------------
__global__ __launch_bounds__(256) void k_readout(
    const float* __restrict__ w_gate, const float* __restrict__ b_gate,
    float* __restrict__ out)
{
    __shared__ float wg[CLS];
    __shared__ float sred[240];
    const int t = threadIdx.x;
    if (t < CLS) wg[t] = w_gate[t];
    __syncthreads();
    const int doc = blockIdx.x;
    const float bg = b_gate[0];
    float acc = 0.f;
    if (t < 240) {
        int c = t % CLS, r = t / CLS;
        for (int p = r; p < LSEQ; p += 12) {
            const float* hr = g_h + (doc*LSEQ + p)*CLS;
            float dot = bg;
            #pragma unroll
            for (int k = 0; k < CLS; k++) dot = fmaf(hr[k], wg[k], dot);
            float gate = 1.f / (1.f + expf(-dot));
            acc = fmaf(gate, hr[c], acc);
        }
        sred[t] = acc;
    }
    __syncthreads();
    if (t < CLS) {
        float s = 0.f;
        #pragma unroll
        for (int r = 0; r < 12; r++) s += sred[r*CLS + t];
        out[doc*CLS + t] = s;
    }
}

// ---------------- launch ----------------
extern "C" void kernel_launch(void* const* d_in, const int* in_sizes, int n_in,
                              void* d_out, int out_size)
{
    const int*   node_ids = (const int*)  d_in[0];
    const float* emb    = (const float*) d_in[4];
    const float* W1     = (const float*) d_in[5];
    const float* b1     = (const float*) d_in[6];
    const float* W2     = (const float*) d_in[7];
    const float* b2     = (const float*) d_in[8];
    const float* gat_W  = (const float*) d_in[9];
    const float* a_src  = (const float*) d_in[10];
    const float* a_dst  = (const float*) d_in[11];
    const float* w_gate = (const float*) d_in[12];
    const float* b_gate = (const float*) d_in[13];
    float* out = (float*)d_out;

    cudaFuncSetAttribute(k_gemm1tc,
        cudaFuncAttributeMaxDynamicSharedMemorySize, GEMM_SMEM);
    cudaFuncSetAttribute(k_gat,
        cudaFuncAttributeMaxDynamicSharedMemorySize, GAT_SMEM);

    k_prepw<<<dim3(DIM/32, HID/32), dim3(32, 8)>>>(W1);                  // 192
    k_gemm1tc<<<NNODES/TM, 256, GEMM_SMEM>>>(node_ids, emb, b1, W2, b2); // 280
    for (int l = 0; l < LAYERS; l++) {
        if (l > 0) k_zero<<<NNODES*CLS/1024, 256>>>(0);                  // zero g_h
        k_gat<<<B_DOCS*HEADS, GT, GAT_SMEM>>>(gat_W, a_src, a_dst, l);   // 1024
    }
    k_readout<<<B_DOCS, 256>>>(w_gate, b_gate, out);
}